// round 4
// baseline (speedup 1.0000x reference)
#include <cuda_runtime.h>
#include <math.h>
#include <stdint.h>

#define HW 4096
#define CH 256
#define NB 4
#define NBC (NB*CH)        // 1024

// ---- scratch (static device globals; no allocation) ----
__device__ float g_mean[2 * NBC];
__device__ float g_rstd[2 * NBC];
__device__ float g_Q[(size_t)NB * HW * CH];
__device__ float g_K[(size_t)NB * HW * CH];
__device__ float g_V[(size_t)NB * HW * CH];

// ---------------- packed f32x2 helpers (sm_103a) ----------------
__device__ __forceinline__ unsigned long long ffma2(unsigned long long a,
                                                    unsigned long long b,
                                                    unsigned long long c) {
    unsigned long long d;
    asm("fma.rn.f32x2 %0, %1, %2, %3;" : "=l"(d) : "l"(a), "l"(b), "l"(c));
    return d;
}
__device__ __forceinline__ unsigned long long fmul2(unsigned long long a,
                                                    unsigned long long b) {
    unsigned long long d;
    asm("mul.rn.f32x2 %0, %1, %2;" : "=l"(d) : "l"(a), "l"(b));
    return d;
}
__device__ __forceinline__ unsigned long long fpack2(float x) {
    unsigned long long d;
    unsigned int xi = __float_as_uint(x);
    asm("mov.b64 %0, {%1, %1};" : "=l"(d) : "r"(xi));
    return d;
}
__device__ __forceinline__ float2 funpack(unsigned long long v) {
    unsigned int lo, hi;
    asm("mov.b64 {%0, %1}, %2;" : "=r"(lo), "=r"(hi) : "l"(v));
    float2 r; r.x = __uint_as_float(lo); r.y = __uint_as_float(hi);
    return r;
}
__device__ __forceinline__ void cpa16(unsigned int dst, const void* src) {
    asm volatile("cp.async.cg.shared.global [%0], [%1], 16;" :: "r"(dst), "l"(src));
}
__device__ __forceinline__ void cpa_commit() {
    asm volatile("cp.async.commit_group;");
}
__device__ __forceinline__ void cpa_wait0() {
    asm volatile("cp.async.wait_group 0;");
}

// =====================================================================
// Stage 1: per-(b,c) mean / rstd for content (idx 0..1023) and style
// (idx 1024..2047). var is unbiased (ddof=1), +1e-5 inside sqrt.
// =====================================================================
__global__ void stats_kernel(const float* __restrict__ content,
                             const float* __restrict__ style) {
    int id = blockIdx.x;                              // 0..2047
    const float* base = (id < NBC ? content : style) + (size_t)(id & (NBC - 1)) * HW;
    float s = 0.f, s2 = 0.f;
    const float4* b4 = (const float4*)base;
    for (int i = threadIdx.x; i < HW / 4; i += 256) {
        float4 v = b4[i];
        s  += v.x + v.y + v.z + v.w;
        s2 += v.x * v.x + v.y * v.y + v.z * v.z + v.w * v.w;
    }
    #pragma unroll
    for (int o = 16; o; o >>= 1) {
        s  += __shfl_xor_sync(~0u, s, o);
        s2 += __shfl_xor_sync(~0u, s2, o);
    }
    __shared__ float sh[8][2];
    int w = threadIdx.x >> 5, l = threadIdx.x & 31;
    if (l == 0) { sh[w][0] = s; sh[w][1] = s2; }
    __syncthreads();
    if (threadIdx.x == 0) {
        s = 0.f; s2 = 0.f;
        #pragma unroll
        for (int i = 0; i < 8; i++) { s += sh[i][0]; s2 += sh[i][1]; }
        float m   = s / (float)HW;
        float var = (s2 - (float)HW * m * m) / (float)(HW - 1);
        g_mean[id] = m;
        g_rstd[id] = rsqrtf(var + 1e-5f);
    }
}

// =====================================================================
// Stage 2: Q/K/V GEMMs (unchanged from passing version).
// =====================================================================
__global__ __launch_bounds__(256) void qkv_gemm(
    const float* __restrict__ content, const float* __restrict__ style,
    const float* __restrict__ Wf, const float* __restrict__ bf,
    const float* __restrict__ Wg, const float* __restrict__ bg,
    const float* __restrict__ Wh, const float* __restrict__ bh)
{
    int z   = blockIdx.z;
    int mat = z % 3, b = z / 3;
    const float *X, *W, *bias;
    float* out;
    int soff;
    if (mat == 0)      { X = content; W = Wf; bias = bf; soff = 0;   out = g_Q; }
    else if (mat == 1) { X = style;   W = Wg; bias = bg; soff = NBC; out = g_K; }
    else               { X = style;   W = Wh; bias = bh; soff = -1;  out = g_V; }
    X   += (size_t)b * CH * HW;
    out += (size_t)b * HW * CH;
    int p0 = blockIdx.x * 128, o0 = blockIdx.y * 64;

    __shared__ float Xs[32][132];   // [channel][pixel], padded
    __shared__ float Ws[64][36];    // [o][channel], padded

    int tid = threadIdx.x;
    int tx  = tid & 15, ty = tid >> 4;
    float acc[8][4];
    #pragma unroll
    for (int u = 0; u < 8; u++)
        #pragma unroll
        for (int v = 0; v < 4; v++) acc[u][v] = 0.f;

    for (int c0 = 0; c0 < CH; c0 += 32) {
        __syncthreads();
        #pragma unroll
        for (int r = 0; r < 4; r++) {
            int e = tid + 256 * r;
            int row = e >> 5, c4 = e & 31;
            float4 v = *(const float4*)(X + (size_t)(c0 + row) * HW + p0 + c4 * 4);
            if (soff >= 0) {
                float m  = g_mean[soff + b * CH + c0 + row];
                float rs = g_rstd[soff + b * CH + c0 + row];
                v.x = (v.x - m) * rs; v.y = (v.y - m) * rs;
                v.z = (v.z - m) * rs; v.w = (v.w - m) * rs;
            }
            *(float4*)&Xs[row][c4 * 4] = v;
        }
        #pragma unroll
        for (int r = 0; r < 2; r++) {
            int e = tid + 256 * r;
            int row = e >> 3, c4 = e & 7;
            *(float4*)&Ws[row][c4 * 4] =
                *(const float4*)(W + (size_t)(o0 + row) * CH + c0 + c4 * 4);
        }
        __syncthreads();
        #pragma unroll
        for (int cc = 0; cc < 32; cc++) {
            float4 x0 = *(float4*)&Xs[cc][tx * 8];
            float4 x1 = *(float4*)&Xs[cc][tx * 8 + 4];
            float w0 = Ws[ty * 4 + 0][cc], w1 = Ws[ty * 4 + 1][cc];
            float w2 = Ws[ty * 4 + 2][cc], w3 = Ws[ty * 4 + 3][cc];
            float xv[8] = {x0.x, x0.y, x0.z, x0.w, x1.x, x1.y, x1.z, x1.w};
            #pragma unroll
            for (int u = 0; u < 8; u++) {
                acc[u][0] += xv[u] * w0;
                acc[u][1] += xv[u] * w1;
                acc[u][2] += xv[u] * w2;
                acc[u][3] += xv[u] * w3;
            }
        }
    }
    float b0 = bias[o0 + ty * 4 + 0], b1 = bias[o0 + ty * 4 + 1];
    float b2 = bias[o0 + ty * 4 + 2], b3 = bias[o0 + ty * 4 + 3];
    #pragma unroll
    for (int u = 0; u < 8; u++) {
        float4 ov = make_float4(acc[u][0] + b0, acc[u][1] + b1,
                                acc[u][2] + b2, acc[u][3] + b3);
        *(float4*)(out + (size_t)(p0 + tx * 8 + u) * CH + o0 + ty * 4) = ov;
    }
}

// =====================================================================
// Stage 3: fused flash attention with packed f32x2 FMAs.
// 256 threads (8 warps). Block handles 2 query tiles of M=64 rows.
// K tile NT=128 keys; Q/K/V tiles in XOR-swizzled smem (float4 groups).
// Scores: thread tile 4 rows x 8 keys, accumulated as f32x2 pairs over
// the channel dim, split into two 4-key half passes (register budget).
// Softmax: warp-local (warp owns rows 8w..8w+7). PV: packed f32x2
// accumulators, V^2 stream fused, V reuses the K smem buffer.
// =====================================================================
#define MQ  64
#define NTK 128
#define PP  132

// float4-group swizzle: logical (row, g) -> physical group
#define SWZ(row, g) (((row) << 6) + ((g) ^ (((row) >> 3) & 7)))

__global__ __launch_bounds__(256, 1) void attn_kernel(
    const float* __restrict__ content, float* __restrict__ out)
{
    extern __shared__ float sm[];
    float* Qs = sm;                    // MQ  * 256
    float* Ks = Qs + MQ * CH;          // NTK * 256 (K, later V)
    float* Ps = Ks + NTK * CH;         // MQ * PP

    unsigned int QsA = (unsigned int)__cvta_generic_to_shared(Qs);
    unsigned int KsA = (unsigned int)__cvta_generic_to_shared(Ks);

    int b    = blockIdx.y;
    int tid  = threadIdx.x;
    int wid  = tid >> 5, lane = tid & 31;
    int tx   = tid & 15, ty = tid >> 4;
    int i0   = ty * 4;                 // 4 query rows per thread (scores)
    int d0   = lane * 8;               // 8-channel slice per lane (PV)

    for (int qt = 0; qt < 2; qt++) {
        int p0 = (blockIdx.x * 2 + qt) * MQ;

        // ---- async-load Q tile (waited inside first kt iteration) ----
        const float4* Qg = (const float4*)(g_Q + ((size_t)b * HW + p0) * CH);
        #pragma unroll
        for (int r = 0; r < 16; r++) {
            int e = tid + 256 * r;     // 4096 float4 slots
            int row = e >> 6, g = e & 63;
            cpa16(QsA + (unsigned int)SWZ(row, g) * 16u, Qg + (size_t)row * 64 + g);
        }
        cpa_commit();

        unsigned long long O1[8][4], O2[8][4];
        #pragma unroll
        for (int rr = 0; rr < 8; rr++)
            #pragma unroll
            for (int u = 0; u < 4; u++) { O1[rr][u] = 0ull; O2[rr][u] = 0ull; }
        float m8[8], l8[8];
        #pragma unroll
        for (int rr = 0; rr < 8; rr++) { m8[rr] = -1e30f; l8[rr] = 0.f; }

        for (int kt = 0; kt < HW / NTK; kt++) {
            __syncthreads();   // prev PV done with Ks(V) and Ps

            // ---- async-load K tile ----
            const float4* Kg = (const float4*)(g_K + ((size_t)b * HW + kt * NTK) * CH);
            #pragma unroll
            for (int r = 0; r < 32; r++) {
                int e = tid + 256 * r;          // 8192 float4 slots
                int row = e >> 6, g = e & 63;
                cpa16(KsA + (unsigned int)SWZ(row, g) * 16u, Kg + (size_t)row * 64 + g);
            }
            cpa_commit();
            cpa_wait0();        // waits Q too on first tile
            __syncthreads();

            // ---- scores: two half passes of 4 rows x 4 keys ----
            #pragma unroll
            for (int jh = 0; jh < 2; jh++) {
                int j0 = tx * 8 + jh * 4;
                const float* qrow[4];
                const float* krow[4];
                int qsw[4], ksw[4];
                #pragma unroll
                for (int ii = 0; ii < 4; ii++) {
                    qrow[ii] = Qs + ((i0 + ii) << 8);
                    qsw[ii]  = ((i0 + ii) >> 3) & 7;
                    krow[ii] = Ks + ((j0 + ii) << 8);
                    ksw[ii]  = ((j0 + ii) >> 3) & 7;
                }
                unsigned long long s2[4][4];
                #pragma unroll
                for (int ii = 0; ii < 4; ii++)
                    #pragma unroll
                    for (int jj = 0; jj < 4; jj++) s2[ii][jj] = 0ull;

                #pragma unroll 4
                for (int k4 = 0; k4 < 64; k4++) {
                    ulonglong2 q[4], kk[4];
                    #pragma unroll
                    for (int ii = 0; ii < 4; ii++)
                        q[ii] = *(const ulonglong2*)(qrow[ii] + ((k4 ^ qsw[ii]) << 2));
                    #pragma unroll
                    for (int jj = 0; jj < 4; jj++)
                        kk[jj] = *(const ulonglong2*)(krow[jj] + ((k4 ^ ksw[jj]) << 2));
                    #pragma unroll
                    for (int ii = 0; ii < 4; ii++)
                        #pragma unroll
                        for (int jj = 0; jj < 4; jj++) {
                            s2[ii][jj] = ffma2(q[ii].x, kk[jj].x, s2[ii][jj]);
                            s2[ii][jj] = ffma2(q[ii].y, kk[jj].y, s2[ii][jj]);
                        }
                }
                #pragma unroll
                for (int ii = 0; ii < 4; ii++) {
                    float2 a0 = funpack(s2[ii][0]);
                    float2 a1 = funpack(s2[ii][1]);
                    float2 a2 = funpack(s2[ii][2]);
                    float2 a3 = funpack(s2[ii][3]);
                    float4 sv = make_float4(a0.x + a0.y, a1.x + a1.y,
                                            a2.x + a2.y, a3.x + a3.y);
                    *(float4*)&Ps[(i0 + ii) * PP + j0] = sv;
                }
            }
            __syncthreads();   // all warps done reading Ks

            // ---- async-load V into the K buffer ----
            const float4* Vg = (const float4*)(g_V + ((size_t)b * HW + kt * NTK) * CH);
            #pragma unroll
            for (int r = 0; r < 32; r++) {
                int e = tid + 256 * r;
                int row = e >> 6, g = e & 63;
                cpa16(KsA + (unsigned int)SWZ(row, g) * 16u, Vg + (size_t)row * 64 + g);
            }
            cpa_commit();

            // ---- warp-local online softmax over this warp's 8 rows ----
            __syncwarp();
            #pragma unroll
            for (int rr = 0; rr < 8; rr++) {
                float* pr = &Ps[(wid * 8 + rr) * PP + lane];
                float s0 = pr[0], s1 = pr[32], s2v = pr[64], s3 = pr[96];
                float mx = fmaxf(fmaxf(s0, s1), fmaxf(s2v, s3));
                #pragma unroll
                for (int o = 16; o; o >>= 1) mx = fmaxf(mx, __shfl_xor_sync(~0u, mx, o));
                float mn   = fmaxf(m8[rr], mx);
                float corr = __expf(m8[rr] - mn);
                float e0 = __expf(s0 - mn), e1 = __expf(s1 - mn);
                float e2 = __expf(s2v - mn), e3 = __expf(s3 - mn);
                float rs = (e0 + e1) + (e2 + e3);
                #pragma unroll
                for (int o = 16; o; o >>= 1) rs += __shfl_xor_sync(~0u, rs, o);
                l8[rr] = l8[rr] * corr + rs;
                m8[rr] = mn;
                pr[0] = e0; pr[32] = e1; pr[64] = e2; pr[96] = e3;
                unsigned long long c2 = fpack2(corr);
                #pragma unroll
                for (int u = 0; u < 4; u++) {
                    O1[rr][u] = fmul2(O1[rr][u], c2);
                    O2[rr][u] = fmul2(O2[rr][u], c2);
                }
            }

            cpa_wait0();
            __syncthreads();   // V ready; all P final

            // ---- P @ [V, V^2], packed accumulators ----
            const float* Pw = &Ps[(wid * 8) * PP];
            #pragma unroll 2
            for (int j = 0; j < NTK; j++) {
                int sw = (j >> 3) & 7;
                const float* vb = Ks + (j << 8);
                ulonglong2 va = *(const ulonglong2*)(vb + (((2 * lane)     ^ sw) << 2));
                ulonglong2 vbq = *(const ulonglong2*)(vb + (((2 * lane + 1) ^ sw) << 2));
                unsigned long long q0 = fmul2(va.x, va.x);
                unsigned long long q1 = fmul2(va.y, va.y);
                unsigned long long q2 = fmul2(vbq.x, vbq.x);
                unsigned long long q3 = fmul2(vbq.y, vbq.y);
                #pragma unroll
                for (int rr = 0; rr < 8; rr++) {
                    unsigned long long pp = fpack2(Pw[rr * PP + j]);
                    O1[rr][0] = ffma2(pp, va.x,  O1[rr][0]);
                    O1[rr][1] = ffma2(pp, va.y,  O1[rr][1]);
                    O1[rr][2] = ffma2(pp, vbq.x, O1[rr][2]);
                    O1[rr][3] = ffma2(pp, vbq.y, O1[rr][3]);
                    O2[rr][0] = ffma2(pp, q0, O2[rr][0]);
                    O2[rr][1] = ffma2(pp, q1, O2[rr][1]);
                    O2[rr][2] = ffma2(pp, q2, O2[rr][2]);
                    O2[rr][3] = ffma2(pp, q3, O2[rr][3]);
                }
            }
        }

        // ---- epilogue ----
        const size_t TSZ = (size_t)NB * CH * HW;
        int boff = b * CH;
        #pragma unroll
        for (int rr = 0; rr < 8; rr++) {
            int p = p0 + wid * 8 + rr;
            float rn = 1.0f / l8[rr];
            #pragma unroll
            for (int u = 0; u < 4; u++) {
                float2 o1 = funpack(O1[rr][u]);
                float2 o2 = funpack(O2[rr][u]);
                #pragma unroll
                for (int h = 0; h < 2; h++) {
                    int c = d0 + u * 2 + h;
                    float mean = (h ? o1.y : o1.x) * rn;
                    float sec  = (h ? o2.y : o2.x) * rn;
                    float sd   = sqrtf(fmaxf(sec - mean * mean, 0.f));
                    size_t idx = (size_t)(boff + c) * HW + p;
                    float nc = (content[idx] - g_mean[boff + c]) * g_rstd[boff + c];
                    out[idx]           = sd * nc + mean;
                    out[idx + TSZ]     = mean;
                    out[idx + 2 * TSZ] = sd;
                }
            }
        }
    }
}

// =====================================================================
extern "C" void kernel_launch(void* const* d_in, const int* in_sizes, int n_in,
                              void* d_out, int out_size) {
    const float* content = (const float*)d_in[0];
    const float* style   = (const float*)d_in[1];
    const float* Wf = (const float*)d_in[2];
    const float* bf = (const float*)d_in[3];
    const float* Wg = (const float*)d_in[4];
    const float* bg = (const float*)d_in[5];
    const float* Wh = (const float*)d_in[6];
    const float* bh = (const float*)d_in[7];
    float* out = (float*)d_out;

    stats_kernel<<<2 * NBC, 256>>>(content, style);
    qkv_gemm<<<dim3(HW / 128, CH / 64, 3 * NB), 256>>>(content, style,
                                                       Wf, bf, Wg, bg, Wh, bh);
    const int smem = (MQ * CH + NTK * CH + MQ * PP) * (int)sizeof(float);
    static bool attr_set = false;
    if (!attr_set) {
        cudaFuncSetAttribute(attn_kernel,
                             cudaFuncAttributeMaxDynamicSharedMemorySize, smem);
        attr_set = true;
    }
    attn_kernel<<<dim3(HW / (2 * MQ), NB), 256, smem>>>(content, out);
}

// round 7
// speedup vs baseline: 2.0948x; 2.0948x over previous
#include <cuda_runtime.h>
#include <cuda_bf16.h>
#include <math.h>
#include <stdint.h>

#define HW 4096
#define CH 256
#define NB 4
#define NBC (NB*CH)

typedef __nv_bfloat16 bf16;

// ---- scratch (static device globals; no allocation) ----
__device__ float g_mean[2 * NBC];
__device__ float g_rstd[2 * NBC];
__device__ bf16 g_Qh[(size_t)NB * HW * CH];
__device__ bf16 g_Ql[(size_t)NB * HW * CH];
__device__ bf16 g_Kh[(size_t)NB * HW * CH];
__device__ bf16 g_Kl[(size_t)NB * HW * CH];
// B for GEMM2: rows 0..255 = V^T [c][p], rows 256..511 = (V^2)^T
__device__ bf16 g_VBh[(size_t)NB * 512 * HW];
__device__ bf16 g_VBl[(size_t)NB * 512 * HW];
__device__ float g_S[(size_t)NB * HW * HW];
__device__ bf16 g_Ph[(size_t)NB * HW * HW];
__device__ bf16 g_Pl[(size_t)NB * HW * HW];
__device__ float g_ms[(size_t)NB * HW * 512];   // [b][q][0:256)=mean, [256:512)=sec

// ---------------- helpers ----------------
__device__ __forceinline__ uint32_t smem_u32(const void* p) {
    return (uint32_t)__cvta_generic_to_shared(p);
}
__device__ __forceinline__ void cpa16(uint32_t dst, const void* src) {
    asm volatile("cp.async.cg.shared.global [%0], [%1], 16;" :: "r"(dst), "l"(src));
}
__device__ __forceinline__ void cpa_commit() { asm volatile("cp.async.commit_group;"); }

__device__ __forceinline__ unsigned long long ffma2(unsigned long long a,
                                                    unsigned long long b,
                                                    unsigned long long c) {
    unsigned long long d;
    asm("fma.rn.f32x2 %0, %1, %2, %3;" : "=l"(d) : "l"(a), "l"(b), "l"(c));
    return d;
}
__device__ __forceinline__ unsigned long long fpack2(float x) {
    unsigned long long d;
    unsigned int xi = __float_as_uint(x);
    asm("mov.b64 %0, {%1, %1};" : "=l"(d) : "r"(xi));
    return d;
}
__device__ __forceinline__ float2 funpack(unsigned long long v) {
    unsigned int lo, hi;
    asm("mov.b64 {%0, %1}, %2;" : "=r"(lo), "=r"(hi) : "l"(v));
    float2 r; r.x = __uint_as_float(lo); r.y = __uint_as_float(hi);
    return r;
}
__device__ __forceinline__ void ldsm4(uint32_t& r0, uint32_t& r1, uint32_t& r2,
                                      uint32_t& r3, uint32_t a) {
    asm volatile("ldmatrix.sync.aligned.m8n8.x4.shared.b16 {%0,%1,%2,%3}, [%4];"
                 : "=r"(r0), "=r"(r1), "=r"(r2), "=r"(r3) : "r"(a));
}
__device__ __forceinline__ void mma16816(float* c, const uint32_t* a, const uint32_t* b) {
    asm volatile("mma.sync.aligned.m16n8k16.row.col.f32.bf16.bf16.f32 "
                 "{%0,%1,%2,%3}, {%4,%5,%6,%7}, {%8,%9}, {%0,%1,%2,%3};"
                 : "+f"(c[0]), "+f"(c[1]), "+f"(c[2]), "+f"(c[3])
                 : "r"(a[0]), "r"(a[1]), "r"(a[2]), "r"(a[3]),
                   "r"(b[0]), "r"(b[1]));
}
__device__ __forceinline__ void split_bf(float x, bf16& h, bf16& l) {
    h = __float2bfloat16_rn(x);
    l = __float2bfloat16_rn(x - __bfloat162float(h));
}

// =====================================================================
// Stage 1: per-(b,c) mean / rstd (ddof=1, +1e-5)
// =====================================================================
__global__ void stats_kernel(const float* __restrict__ content,
                             const float* __restrict__ style) {
    int id = blockIdx.x;
    const float* base = (id < NBC ? content : style) + (size_t)(id & (NBC - 1)) * HW;
    float s = 0.f, s2 = 0.f;
    const float4* b4 = (const float4*)base;
    for (int i = threadIdx.x; i < HW / 4; i += 256) {
        float4 v = b4[i];
        s  += v.x + v.y + v.z + v.w;
        s2 += v.x * v.x + v.y * v.y + v.z * v.z + v.w * v.w;
    }
    #pragma unroll
    for (int o = 16; o; o >>= 1) {
        s  += __shfl_xor_sync(~0u, s, o);
        s2 += __shfl_xor_sync(~0u, s2, o);
    }
    __shared__ float sh[8][2];
    int w = threadIdx.x >> 5, l = threadIdx.x & 31;
    if (l == 0) { sh[w][0] = s; sh[w][1] = s2; }
    __syncthreads();
    if (threadIdx.x == 0) {
        s = 0.f; s2 = 0.f;
        #pragma unroll
        for (int i = 0; i < 8; i++) { s += sh[i][0]; s2 += sh[i][1]; }
        float m   = s / (float)HW;
        float var = (s2 - (float)HW * m * m) / (float)(HW - 1);
        g_mean[id] = m;
        g_rstd[id] = rsqrtf(var + 1e-5f);
    }
}

// =====================================================================
// Stage 2: Q/K/V 1x1 convs (f32x2 inner loop); split-bf16 outputs.
// Q/K -> [b][p][c] hi/lo.  V -> g_VB rows c (V^T) and c+256 ((V^2)^T).
// =====================================================================
__global__ __launch_bounds__(256) void qkv_gemm(
    const float* __restrict__ content, const float* __restrict__ style,
    const float* __restrict__ Wf, const float* __restrict__ bfb,
    const float* __restrict__ Wg, const float* __restrict__ bg,
    const float* __restrict__ Wh, const float* __restrict__ bh)
{
    int z = blockIdx.z;
    int mat = z % 3, b = z / 3;
    const float *X, *W, *bias;
    int soff;
    if (mat == 0)      { X = content; W = Wf; bias = bfb; soff = 0;   }
    else if (mat == 1) { X = style;   W = Wg; bias = bg;  soff = NBC; }
    else               { X = style;   W = Wh; bias = bh;  soff = -1;  }
    X += (size_t)b * CH * HW;
    int p0 = blockIdx.x * 128, o0 = blockIdx.y * 64;

    __shared__ float Xs[32][132];
    __shared__ float Ws[64][36];

    int tid = threadIdx.x;
    int tx  = tid & 15, ty = tid >> 4;
    unsigned long long acc2[4][4];
    #pragma unroll
    for (int u = 0; u < 4; u++)
        #pragma unroll
        for (int v = 0; v < 4; v++) acc2[u][v] = 0ull;

    for (int c0 = 0; c0 < CH; c0 += 32) {
        __syncthreads();
        #pragma unroll
        for (int r = 0; r < 4; r++) {
            int e = tid + 256 * r;
            int row = e >> 5, c4 = e & 31;
            float4 v = *(const float4*)(X + (size_t)(c0 + row) * HW + p0 + c4 * 4);
            if (soff >= 0) {
                float m  = g_mean[soff + b * CH + c0 + row];
                float rs = g_rstd[soff + b * CH + c0 + row];
                v.x = (v.x - m) * rs; v.y = (v.y - m) * rs;
                v.z = (v.z - m) * rs; v.w = (v.w - m) * rs;
            }
            *(float4*)&Xs[row][c4 * 4] = v;
        }
        #pragma unroll
        for (int r = 0; r < 2; r++) {
            int e = tid + 256 * r;
            int row = e >> 3, c4 = e & 7;
            *(float4*)&Ws[row][c4 * 4] =
                *(const float4*)(W + (size_t)(o0 + row) * CH + c0 + c4 * 4);
        }
        __syncthreads();
        #pragma unroll
        for (int cc = 0; cc < 32; cc++) {
            ulonglong2 x01 = *(ulonglong2*)&Xs[cc][tx * 8];
            ulonglong2 x23 = *(ulonglong2*)&Xs[cc][tx * 8 + 4];
            unsigned long long xv2[4] = {x01.x, x01.y, x23.x, x23.y};
            unsigned long long wp0 = fpack2(Ws[ty * 4 + 0][cc]);
            unsigned long long wp1 = fpack2(Ws[ty * 4 + 1][cc]);
            unsigned long long wp2 = fpack2(Ws[ty * 4 + 2][cc]);
            unsigned long long wp3 = fpack2(Ws[ty * 4 + 3][cc]);
            #pragma unroll
            for (int u = 0; u < 4; u++) {
                acc2[u][0] = ffma2(xv2[u], wp0, acc2[u][0]);
                acc2[u][1] = ffma2(xv2[u], wp1, acc2[u][1]);
                acc2[u][2] = ffma2(xv2[u], wp2, acc2[u][2]);
                acc2[u][3] = ffma2(xv2[u], wp3, acc2[u][3]);
            }
        }
    }
    float bv[4] = {bias[o0 + ty * 4 + 0], bias[o0 + ty * 4 + 1],
                   bias[o0 + ty * 4 + 2], bias[o0 + ty * 4 + 3]};
    float accv[8][4];
    #pragma unroll
    for (int u = 0; u < 4; u++)
        #pragma unroll
        for (int v = 0; v < 4; v++) {
            float2 t = funpack(acc2[u][v]);
            accv[2 * u][v] = t.x + bv[v];
            accv[2 * u + 1][v] = t.y + bv[v];
        }

    if (mat < 2) {
        bf16* oh = (mat ? g_Kh : g_Qh) + (size_t)b * HW * CH;
        bf16* ol = (mat ? g_Kl : g_Ql) + (size_t)b * HW * CH;
        #pragma unroll
        for (int u = 0; u < 8; u++) {
            size_t ix = (size_t)(p0 + tx * 8 + u) * CH + o0 + ty * 4;
            bf16 h[4], l[4];
            #pragma unroll
            for (int v = 0; v < 4; v++) split_bf(accv[u][v], h[v], l[v]);
            *(uint2*)(oh + ix) = *(uint2*)h;
            *(uint2*)(ol + ix) = *(uint2*)l;
        }
    } else {
        size_t vb = (size_t)b * 512 * HW;
        #pragma unroll
        for (int v = 0; v < 4; v++) {
            int c = o0 + ty * 4 + v;
            size_t ix  = vb + (size_t)c * HW + p0 + tx * 8;
            size_t ix2 = vb + (size_t)(c + 256) * HW + p0 + tx * 8;
            bf16 hv[8], lv[8], h2[8], l2[8];
            #pragma unroll
            for (int u = 0; u < 8; u++) {
                float x = accv[u][v];
                split_bf(x, hv[u], lv[u]);
                split_bf(x * x, h2[u], l2[u]);
            }
            *(uint4*)(g_VBh + ix)  = *(uint4*)hv;
            *(uint4*)(g_VBl + ix)  = *(uint4*)lv;
            *(uint4*)(g_VBh + ix2) = *(uint4*)h2;
            *(uint4*)(g_VBl + ix2) = *(uint4*)l2;
        }
    }
}

// =====================================================================
// Shared split-bf16 mma.sync GEMM:  C[M x N] = (Ah+Al) . (Bh+Bl)^T
// A: [m][k] row-major, B: [n][k] row-major (both bf16 hi/lo).
// Block 128x128, 8 warps (warp tile 32x64), k-chunk 32, double buffer.
// =====================================================================
#define PADH  40                    // halves per smem row (32 data + 8 pad)
#define TILEB (128 * PADH * 2)      // 10240 B per matrix tile
#define STAGEB (4 * TILEB)          // 40960 B
#define GSMEM (2 * STAGEB)          // 81920 B

__global__ __launch_bounds__(256, 1) void mma_gemm(
    const bf16* __restrict__ Ah_, const bf16* __restrict__ Al_,
    const bf16* __restrict__ Bh_, const bf16* __restrict__ Bl_,
    float* __restrict__ C_, int K, int ldc,
    unsigned long long aS, unsigned long long bS, unsigned long long cS)
{
    extern __shared__ char gsm[];
    uint32_t smb = smem_u32(gsm);
    int b = blockIdx.z, m0 = blockIdx.y * 128, n0 = blockIdx.x * 128;
    int tid = threadIdx.x, lane = tid & 31, wid = tid >> 5;
    int wm = wid & 3, wn = wid >> 2;

    const bf16* gsrc[4];
    gsrc[0] = Ah_ + b * aS + (size_t)m0 * K;
    gsrc[1] = Al_ + b * aS + (size_t)m0 * K;
    gsrc[2] = Bh_ + b * bS + (size_t)n0 * K;
    gsrc[3] = Bl_ + b * bS + (size_t)n0 * K;

    float Cf[2][8][4];
    #pragma unroll
    for (int mi = 0; mi < 2; mi++)
        #pragma unroll
        for (int nj = 0; nj < 8; nj++)
            #pragma unroll
            for (int q = 0; q < 4; q++) Cf[mi][nj][q] = 0.f;

    // ldmatrix per-lane byte offsets within a stage
    uint32_t aoff[2], boff[4];
    #pragma unroll
    for (int mi = 0; mi < 2; mi++)
        aoff[mi] = ((uint32_t)(wm * 32 + mi * 16 + (lane & 15)) * PADH +
                    ((lane >> 4) << 3)) * 2u;
    #pragma unroll
    for (int njp = 0; njp < 4; njp++)
        boff[njp] = ((uint32_t)(wn * 64 + njp * 16 + (lane & 7) + ((lane >> 4) << 3)) * PADH +
                     (((lane >> 3) & 1) << 3)) * 2u;

    int nch = K >> 5;

    // chunk loader: 2048 16B pieces / 256 threads = 8 each
    auto load_chunk = [&](int ch, int st) {
        int k0 = ch << 5;
        uint32_t dbase = smb + (uint32_t)st * STAGEB;
        #pragma unroll
        for (int t = 0; t < 8; t++) {
            int e = tid + (t << 8);
            int matq = e >> 9, rem = e & 511;
            int row = rem >> 2, cc = rem & 3;
            cpa16(dbase + (uint32_t)matq * TILEB + (uint32_t)(row * PADH) * 2u + cc * 16,
                  gsrc[matq] + (size_t)row * K + k0 + cc * 8);
        }
        cpa_commit();
    };

    load_chunk(0, 0);
    for (int ch = 0; ch < nch; ch++) {
        int st = ch & 1;
        if (ch + 1 < nch) {
            load_chunk(ch + 1, st ^ 1);
            asm volatile("cp.async.wait_group 1;");
        } else {
            asm volatile("cp.async.wait_group 0;");
        }
        __syncthreads();
        uint32_t sbase = smb + (uint32_t)st * STAGEB;
        #pragma unroll
        for (int ks = 0; ks < 2; ks++) {
            uint32_t kb = sbase + (ks << 5);
            uint32_t Afh[2][4], Afl[2][4], Bfh[8][2], Bfl[8][2];
            #pragma unroll
            for (int mi = 0; mi < 2; mi++) {
                ldsm4(Afh[mi][0], Afh[mi][1], Afh[mi][2], Afh[mi][3], kb + aoff[mi]);
                ldsm4(Afl[mi][0], Afl[mi][1], Afl[mi][2], Afl[mi][3],
                      kb + TILEB + aoff[mi]);
            }
            #pragma unroll
            for (int njp = 0; njp < 4; njp++) {
                uint32_t r0, r1, r2, r3;
                ldsm4(r0, r1, r2, r3, kb + 2 * TILEB + boff[njp]);
                Bfh[2 * njp][0] = r0; Bfh[2 * njp][1] = r1;
                Bfh[2 * njp + 1][0] = r2; Bfh[2 * njp + 1][1] = r3;
                ldsm4(r0, r1, r2, r3, kb + 3 * TILEB + boff[njp]);
                Bfl[2 * njp][0] = r0; Bfl[2 * njp][1] = r1;
                Bfl[2 * njp + 1][0] = r2; Bfl[2 * njp + 1][1] = r3;
            }
            #pragma unroll
            for (int mi = 0; mi < 2; mi++)
                #pragma unroll
                for (int nj = 0; nj < 8; nj++) {
                    mma16816(Cf[mi][nj], Afh[mi], Bfh[nj]);
                    mma16816(Cf[mi][nj], Afh[mi], Bfl[nj]);
                    mma16816(Cf[mi][nj], Afl[mi], Bfh[nj]);
                }
        }
        __syncthreads();
    }

    float* Cb = C_ + b * cS + (size_t)m0 * ldc + n0;
    int r0 = wm * 32 + (lane >> 2);
    int c0 = wn * 64 + ((lane & 3) << 1);
    #pragma unroll
    for (int mi = 0; mi < 2; mi++)
        #pragma unroll
        for (int nj = 0; nj < 8; nj++) {
            int r = r0 + mi * 16, c = c0 + nj * 8;
            *(float2*)&Cb[(size_t)r * ldc + c] =
                make_float2(Cf[mi][nj][0], Cf[mi][nj][1]);
            *(float2*)&Cb[(size_t)(r + 8) * ldc + c] =
                make_float2(Cf[mi][nj][2], Cf[mi][nj][3]);
        }
}

// =====================================================================
// Softmax over each S row; write P split to bf16 hi/lo.
// Row = 4096 floats = 1024 float4; 256 threads x 4 iters, stride 256.
// =====================================================================
__global__ __launch_bounds__(256) void softmax_kernel() {
    int row = blockIdx.x, b = blockIdx.y;
    size_t base = ((size_t)b * HW + row) * HW;
    const float4* src = (const float4*)(g_S + base);
    int tid = threadIdx.x;
    float4 v[4];
    float mx = -1e30f;
    #pragma unroll
    for (int i = 0; i < 4; i++) {
        v[i] = src[tid + i * 256];
        mx = fmaxf(mx, fmaxf(fmaxf(v[i].x, v[i].y), fmaxf(v[i].z, v[i].w)));
    }
    __shared__ float red[16];
    #pragma unroll
    for (int o = 16; o; o >>= 1) mx = fmaxf(mx, __shfl_xor_sync(~0u, mx, o));
    int w = tid >> 5;
    if ((tid & 31) == 0) red[w] = mx;
    __syncthreads();
    float bm = red[0];
    #pragma unroll
    for (int i = 1; i < 8; i++) bm = fmaxf(bm, red[i]);
    float sum = 0.f;
    #pragma unroll
    for (int i = 0; i < 4; i++) {
        v[i].x = __expf(v[i].x - bm); v[i].y = __expf(v[i].y - bm);
        v[i].z = __expf(v[i].z - bm); v[i].w = __expf(v[i].w - bm);
        sum += (v[i].x + v[i].y) + (v[i].z + v[i].w);
    }
    #pragma unroll
    for (int o = 16; o; o >>= 1) sum += __shfl_xor_sync(~0u, sum, o);
    if ((tid & 31) == 0) red[8 + w] = sum;
    __syncthreads();
    float bs = 0.f;
    #pragma unroll
    for (int i = 0; i < 8; i++) bs += red[8 + i];
    float rinv = 1.0f / bs;
    #pragma unroll
    for (int i = 0; i < 4; i++) {
        float p[4] = {v[i].x * rinv, v[i].y * rinv, v[i].z * rinv, v[i].w * rinv};
        bf16 h[4], l[4];
        #pragma unroll
        for (int k = 0; k < 4; k++) split_bf(p[k], h[k], l[k]);
        size_t ix = base + (size_t)(tid + i * 256) * 4;
        *(uint2*)(g_Ph + ix) = *(uint2*)h;
        *(uint2*)(g_Pl + ix) = *(uint2*)l;
    }
}

// =====================================================================
// Epilogue: read g_ms [b][q][512] (mean|sec), transpose to [b][c][p];
// out = std * norm(content) + mean; outputs concatenated (out|mean|std).
// =====================================================================
#define EPSM (2 * 256 * 33 * 4)
__global__ __launch_bounds__(256) void epilogue_kernel(
    const float* __restrict__ content, float* __restrict__ out) {
    extern __shared__ float esm[];
    float* ms = esm;              // [256][33]
    float* ss = esm + 256 * 33;
    int p0 = blockIdx.x * 32, b = blockIdx.y;
    int tid = threadIdx.x, w = tid >> 5, lane = tid & 31;
    #pragma unroll
    for (int it = 0; it < 8; it++) {
        int e = tid + (it << 8);
        int row = e >> 6;            // 0..31
        int c4 = (e & 63) << 2;      // 0..252
        const float* src = g_ms + ((size_t)b * HW + p0 + row) * 512;
        float4 mv = *(const float4*)(src + c4);
        float4 sv = *(const float4*)(src + 256 + c4);
        ms[(c4 + 0) * 33 + row] = mv.x; ms[(c4 + 1) * 33 + row] = mv.y;
        ms[(c4 + 2) * 33 + row] = mv.z; ms[(c4 + 3) * 33 + row] = mv.w;
        ss[(c4 + 0) * 33 + row] = sv.x; ss[(c4 + 1) * 33 + row] = sv.y;
        ss[(c4 + 2) * 33 + row] = sv.z; ss[(c4 + 3) * 33 + row] = sv.w;
    }
    __syncthreads();
    const size_t TSZ = (size_t)NB * CH * HW;
    #pragma unroll 4
    for (int g = 0; g < 32; g++) {
        int c = w * 32 + g;
        float mean = ms[c * 33 + lane];
        float sec  = ss[c * 33 + lane];
        float sd   = sqrtf(fmaxf(sec - mean * mean, 0.f));
        size_t idx = ((size_t)b * CH + c) * HW + p0 + lane;
        float nc = (content[idx] - g_mean[b * CH + c]) * g_rstd[b * CH + c];
        out[idx]           = sd * nc + mean;
        out[idx + TSZ]     = mean;
        out[idx + 2 * TSZ] = sd;
    }
}

// =====================================================================
extern "C" void kernel_launch(void* const* d_in, const int* in_sizes, int n_in,
                              void* d_out, int out_size) {
    const float* content = (const float*)d_in[0];
    const float* style   = (const float*)d_in[1];
    const float* Wf = (const float*)d_in[2];
    const float* bfp = (const float*)d_in[3];
    const float* Wg = (const float*)d_in[4];
    const float* bg = (const float*)d_in[5];
    const float* Wh = (const float*)d_in[6];
    const float* bh = (const float*)d_in[7];
    float* out = (float*)d_out;

    static bool init = false;
    static bf16 *pQh, *pQl, *pKh, *pKl, *pVBh, *pVBl, *pPh, *pPl;
    static float *pS, *pMS;
    if (!init) {
        cudaGetSymbolAddress((void**)&pQh, g_Qh);
        cudaGetSymbolAddress((void**)&pQl, g_Ql);
        cudaGetSymbolAddress((void**)&pKh, g_Kh);
        cudaGetSymbolAddress((void**)&pKl, g_Kl);
        cudaGetSymbolAddress((void**)&pVBh, g_VBh);
        cudaGetSymbolAddress((void**)&pVBl, g_VBl);
        cudaGetSymbolAddress((void**)&pPh, g_Ph);
        cudaGetSymbolAddress((void**)&pPl, g_Pl);
        cudaGetSymbolAddress((void**)&pS, g_S);
        cudaGetSymbolAddress((void**)&pMS, g_ms);
        cudaFuncSetAttribute(mma_gemm,
                             cudaFuncAttributeMaxDynamicSharedMemorySize, GSMEM);
        cudaFuncSetAttribute(epilogue_kernel,
                             cudaFuncAttributeMaxDynamicSharedMemorySize, EPSM);
        init = true;
    }

    stats_kernel<<<2 * NBC, 256>>>(content, style);
    qkv_gemm<<<dim3(HW / 128, CH / 64, 3 * NB), 256>>>(content, style,
                                                       Wf, bfp, Wg, bg, Wh, bh);
    // GEMM1: S = Qn . Kn^T   (M=N=4096, K=256)
    mma_gemm<<<dim3(HW / 128, HW / 128, NB), 256, GSMEM>>>(
        pQh, pQl, pKh, pKl, pS, CH, HW,
        (unsigned long long)HW * CH, (unsigned long long)HW * CH,
        (unsigned long long)HW * HW);
    softmax_kernel<<<dim3(HW, NB), 256>>>();
    // GEMM2: [mean|sec] = P . [V^T ; V2^T]^T  (M=4096, N=512, K=4096)
    mma_gemm<<<dim3(512 / 128, HW / 128, NB), 256, GSMEM>>>(
        pPh, pPl, pVBh, pVBl, pMS, HW, 512,
        (unsigned long long)HW * HW, (unsigned long long)512 * HW,
        (unsigned long long)HW * 512);
    epilogue_kernel<<<dim3(HW / 32, NB), 256, EPSM>>>(content, out);
}

// round 8
// speedup vs baseline: 2.1681x; 1.0350x over previous
#include <cuda_runtime.h>
#include <cuda_bf16.h>
#include <math.h>
#include <stdint.h>

#define HW 4096
#define CH 256
#define NB 4
#define NBC (NB*CH)
#define KSPLIT 4

typedef __nv_bfloat16 bf16;

// ---- scratch (static device globals; no allocation) ----
__device__ float g_mean[2 * NBC];
__device__ float g_rstd[2 * NBC];
__device__ bf16 g_Qh[(size_t)NB * HW * CH];
__device__ bf16 g_Ql[(size_t)NB * HW * CH];
__device__ bf16 g_Kh[(size_t)NB * HW * CH];
__device__ bf16 g_Kl[(size_t)NB * HW * CH];
// B for GEMM2: rows 0..255 = V^T [c][p], rows 256..511 = (V^2)^T
__device__ bf16 g_VBh[(size_t)NB * 512 * HW];
__device__ bf16 g_VBl[(size_t)NB * 512 * HW];
__device__ float g_S[(size_t)NB * HW * HW];
__device__ bf16 g_Ph[(size_t)NB * HW * HW];
__device__ bf16 g_Pl[(size_t)NB * HW * HW];
// split-K partials: [slice][b][q][0:256)=mean, [256:512)=sec
__device__ float g_ms[(size_t)KSPLIT * NB * HW * 512];

// ---------------- helpers ----------------
__device__ __forceinline__ uint32_t smem_u32(const void* p) {
    return (uint32_t)__cvta_generic_to_shared(p);
}
__device__ __forceinline__ void cpa16(uint32_t dst, const void* src) {
    asm volatile("cp.async.cg.shared.global [%0], [%1], 16;" :: "r"(dst), "l"(src));
}
__device__ __forceinline__ void cpa_commit() { asm volatile("cp.async.commit_group;"); }

__device__ __forceinline__ unsigned long long ffma2(unsigned long long a,
                                                    unsigned long long b,
                                                    unsigned long long c) {
    unsigned long long d;
    asm("fma.rn.f32x2 %0, %1, %2, %3;" : "=l"(d) : "l"(a), "l"(b), "l"(c));
    return d;
}
__device__ __forceinline__ unsigned long long fpack2(float x) {
    unsigned long long d;
    unsigned int xi = __float_as_uint(x);
    asm("mov.b64 %0, {%1, %1};" : "=l"(d) : "r"(xi));
    return d;
}
__device__ __forceinline__ float2 funpack(unsigned long long v) {
    unsigned int lo, hi;
    asm("mov.b64 {%0, %1}, %2;" : "=r"(lo), "=r"(hi) : "l"(v));
    float2 r; r.x = __uint_as_float(lo); r.y = __uint_as_float(hi);
    return r;
}
__device__ __forceinline__ void ldsm4(uint32_t& r0, uint32_t& r1, uint32_t& r2,
                                      uint32_t& r3, uint32_t a) {
    asm volatile("ldmatrix.sync.aligned.m8n8.x4.shared.b16 {%0,%1,%2,%3}, [%4];"
                 : "=r"(r0), "=r"(r1), "=r"(r2), "=r"(r3) : "r"(a));
}
__device__ __forceinline__ void mma16816(float* c, const uint32_t* a, const uint32_t* b) {
    asm volatile("mma.sync.aligned.m16n8k16.row.col.f32.bf16.bf16.f32 "
                 "{%0,%1,%2,%3}, {%4,%5,%6,%7}, {%8,%9}, {%0,%1,%2,%3};"
                 : "+f"(c[0]), "+f"(c[1]), "+f"(c[2]), "+f"(c[3])
                 : "r"(a[0]), "r"(a[1]), "r"(a[2]), "r"(a[3]),
                   "r"(b[0]), "r"(b[1]));
}
__device__ __forceinline__ void split_bf(float x, bf16& h, bf16& l) {
    h = __float2bfloat16_rn(x);
    l = __float2bfloat16_rn(x - __bfloat162float(h));
}

// =====================================================================
// Stage 1: per-(b,c) mean / rstd (ddof=1, +1e-5)
// =====================================================================
__global__ void stats_kernel(const float* __restrict__ content,
                             const float* __restrict__ style) {
    int id = blockIdx.x;
    const float* base = (id < NBC ? content : style) + (size_t)(id & (NBC - 1)) * HW;
    float s = 0.f, s2 = 0.f;
    const float4* b4 = (const float4*)base;
    for (int i = threadIdx.x; i < HW / 4; i += 256) {
        float4 v = b4[i];
        s  += v.x + v.y + v.z + v.w;
        s2 += v.x * v.x + v.y * v.y + v.z * v.z + v.w * v.w;
    }
    #pragma unroll
    for (int o = 16; o; o >>= 1) {
        s  += __shfl_xor_sync(~0u, s, o);
        s2 += __shfl_xor_sync(~0u, s2, o);
    }
    __shared__ float sh[8][2];
    int w = threadIdx.x >> 5, l = threadIdx.x & 31;
    if (l == 0) { sh[w][0] = s; sh[w][1] = s2; }
    __syncthreads();
    if (threadIdx.x == 0) {
        s = 0.f; s2 = 0.f;
        #pragma unroll
        for (int i = 0; i < 8; i++) { s += sh[i][0]; s2 += sh[i][1]; }
        float m   = s / (float)HW;
        float var = (s2 - (float)HW * m * m) / (float)(HW - 1);
        g_mean[id] = m;
        g_rstd[id] = rsqrtf(var + 1e-5f);
    }
}

// =====================================================================
// Stage 2: Q/K/V 1x1 convs (f32x2 inner loop); split-bf16 outputs.
// Q/K -> [b][p][c] hi/lo.  V -> g_VB rows c (V^T) and c+256 ((V^2)^T).
// =====================================================================
__global__ __launch_bounds__(256) void qkv_gemm(
    const float* __restrict__ content, const float* __restrict__ style,
    const float* __restrict__ Wf, const float* __restrict__ bfb,
    const float* __restrict__ Wg, const float* __restrict__ bg,
    const float* __restrict__ Wh, const float* __restrict__ bh)
{
    int z = blockIdx.z;
    int mat = z % 3, b = z / 3;
    const float *X, *W, *bias;
    int soff;
    if (mat == 0)      { X = content; W = Wf; bias = bfb; soff = 0;   }
    else if (mat == 1) { X = style;   W = Wg; bias = bg;  soff = NBC; }
    else               { X = style;   W = Wh; bias = bh;  soff = -1;  }
    X += (size_t)b * CH * HW;
    int p0 = blockIdx.x * 128, o0 = blockIdx.y * 64;

    __shared__ float Xs[32][132];
    __shared__ float Ws[64][36];

    int tid = threadIdx.x;
    int tx  = tid & 15, ty = tid >> 4;
    unsigned long long acc2[4][4];
    #pragma unroll
    for (int u = 0; u < 4; u++)
        #pragma unroll
        for (int v = 0; v < 4; v++) acc2[u][v] = 0ull;

    for (int c0 = 0; c0 < CH; c0 += 32) {
        __syncthreads();
        #pragma unroll
        for (int r = 0; r < 4; r++) {
            int e = tid + 256 * r;
            int row = e >> 5, c4 = e & 31;
            float4 v = *(const float4*)(X + (size_t)(c0 + row) * HW + p0 + c4 * 4);
            if (soff >= 0) {
                float m  = g_mean[soff + b * CH + c0 + row];
                float rs = g_rstd[soff + b * CH + c0 + row];
                v.x = (v.x - m) * rs; v.y = (v.y - m) * rs;
                v.z = (v.z - m) * rs; v.w = (v.w - m) * rs;
            }
            *(float4*)&Xs[row][c4 * 4] = v;
        }
        #pragma unroll
        for (int r = 0; r < 2; r++) {
            int e = tid + 256 * r;
            int row = e >> 3, c4 = e & 7;
            *(float4*)&Ws[row][c4 * 4] =
                *(const float4*)(W + (size_t)(o0 + row) * CH + c0 + c4 * 4);
        }
        __syncthreads();
        #pragma unroll
        for (int cc = 0; cc < 32; cc++) {
            ulonglong2 x01 = *(ulonglong2*)&Xs[cc][tx * 8];
            ulonglong2 x23 = *(ulonglong2*)&Xs[cc][tx * 8 + 4];
            unsigned long long xv2[4] = {x01.x, x01.y, x23.x, x23.y};
            unsigned long long wp0 = fpack2(Ws[ty * 4 + 0][cc]);
            unsigned long long wp1 = fpack2(Ws[ty * 4 + 1][cc]);
            unsigned long long wp2 = fpack2(Ws[ty * 4 + 2][cc]);
            unsigned long long wp3 = fpack2(Ws[ty * 4 + 3][cc]);
            #pragma unroll
            for (int u = 0; u < 4; u++) {
                acc2[u][0] = ffma2(xv2[u], wp0, acc2[u][0]);
                acc2[u][1] = ffma2(xv2[u], wp1, acc2[u][1]);
                acc2[u][2] = ffma2(xv2[u], wp2, acc2[u][2]);
                acc2[u][3] = ffma2(xv2[u], wp3, acc2[u][3]);
            }
        }
    }
    float bv[4] = {bias[o0 + ty * 4 + 0], bias[o0 + ty * 4 + 1],
                   bias[o0 + ty * 4 + 2], bias[o0 + ty * 4 + 3]};
    float accv[8][4];
    #pragma unroll
    for (int u = 0; u < 4; u++)
        #pragma unroll
        for (int v = 0; v < 4; v++) {
            float2 t = funpack(acc2[u][v]);
            accv[2 * u][v] = t.x + bv[v];
            accv[2 * u + 1][v] = t.y + bv[v];
        }

    if (mat < 2) {
        bf16* oh = (mat ? g_Kh : g_Qh) + (size_t)b * HW * CH;
        bf16* ol = (mat ? g_Kl : g_Ql) + (size_t)b * HW * CH;
        #pragma unroll
        for (int u = 0; u < 8; u++) {
            size_t ix = (size_t)(p0 + tx * 8 + u) * CH + o0 + ty * 4;
            bf16 h[4], l[4];
            #pragma unroll
            for (int v = 0; v < 4; v++) split_bf(accv[u][v], h[v], l[v]);
            *(uint2*)(oh + ix) = *(uint2*)h;
            *(uint2*)(ol + ix) = *(uint2*)l;
        }
    } else {
        size_t vb = (size_t)b * 512 * HW;
        #pragma unroll
        for (int v = 0; v < 4; v++) {
            int c = o0 + ty * 4 + v;
            size_t ix  = vb + (size_t)c * HW + p0 + tx * 8;
            size_t ix2 = vb + (size_t)(c + 256) * HW + p0 + tx * 8;
            bf16 hv[8], lv[8], h2[8], l2[8];
            #pragma unroll
            for (int u = 0; u < 8; u++) {
                float x = accv[u][v];
                split_bf(x, hv[u], lv[u]);
                split_bf(x * x, h2[u], l2[u]);
            }
            *(uint4*)(g_VBh + ix)  = *(uint4*)hv;
            *(uint4*)(g_VBl + ix)  = *(uint4*)lv;
            *(uint4*)(g_VBh + ix2) = *(uint4*)h2;
            *(uint4*)(g_VBl + ix2) = *(uint4*)l2;
        }
    }
}

// =====================================================================
// Shared split-bf16 mma.sync GEMM:  C = (Ah+Al).(Bh+Bl)^T over a K slice
// A: [m][k] row-major (stride Ktot), B: [n][k] row-major (stride Ktot).
// Block 128x128, 8 warps (warp tile 32x64), k-chunk 32, 3-stage pipeline.
// Split-K: blockIdx.z encodes (b, slice); slice s covers K [s*Klen, ...).
// =====================================================================
#define PADH  40                    // halves per smem row (32 data + 8 pad)
#define TILEB (128 * PADH * 2)      // 10240 B per matrix tile
#define STAGEB (4 * TILEB)          // 40960 B
#define NSTAGE 3
#define GSMEM (NSTAGE * STAGEB)     // 122880 B

__global__ __launch_bounds__(256, 1) void mma_gemm(
    const bf16* __restrict__ Ah_, const bf16* __restrict__ Al_,
    const bf16* __restrict__ Bh_, const bf16* __restrict__ Bl_,
    float* __restrict__ C_, int Klen, int Ktot, int ldc,
    unsigned long long aS, unsigned long long bS, unsigned long long cS,
    unsigned long long sliceS, int nslice)
{
    extern __shared__ char gsm[];
    uint32_t smb = smem_u32(gsm);
    int b = blockIdx.z / nslice, slice = blockIdx.z % nslice;
    int koff = slice * Klen;
    int m0 = blockIdx.y * 128, n0 = blockIdx.x * 128;
    int tid = threadIdx.x, lane = tid & 31, wid = tid >> 5;
    int wm = wid & 3, wn = wid >> 2;

    const bf16* gsrc[4];
    gsrc[0] = Ah_ + b * aS + (size_t)m0 * Ktot + koff;
    gsrc[1] = Al_ + b * aS + (size_t)m0 * Ktot + koff;
    gsrc[2] = Bh_ + b * bS + (size_t)n0 * Ktot + koff;
    gsrc[3] = Bl_ + b * bS + (size_t)n0 * Ktot + koff;

    float Cf[2][8][4];
    #pragma unroll
    for (int mi = 0; mi < 2; mi++)
        #pragma unroll
        for (int nj = 0; nj < 8; nj++)
            #pragma unroll
            for (int q = 0; q < 4; q++) Cf[mi][nj][q] = 0.f;

    // ldmatrix per-lane byte offsets within a stage
    uint32_t aoff[2], boff[4];
    #pragma unroll
    for (int mi = 0; mi < 2; mi++)
        aoff[mi] = ((uint32_t)(wm * 32 + mi * 16 + (lane & 15)) * PADH +
                    ((lane >> 4) << 3)) * 2u;
    #pragma unroll
    for (int njp = 0; njp < 4; njp++)
        boff[njp] = ((uint32_t)(wn * 64 + njp * 16 + (lane & 7) + ((lane >> 4) << 3)) * PADH +
                     (((lane >> 3) & 1) << 3)) * 2u;

    int nch = Klen >> 5;

    // chunk loader: 2048 16B pieces / 256 threads = 8 each
    auto load_chunk = [&](int ch) {
        int k0 = ch << 5;
        uint32_t dbase = smb + (uint32_t)(ch % NSTAGE) * STAGEB;
        #pragma unroll
        for (int t = 0; t < 8; t++) {
            int e = tid + (t << 8);
            int matq = e >> 9, rem = e & 511;
            int row = rem >> 2, cc = rem & 3;
            cpa16(dbase + (uint32_t)matq * TILEB + (uint32_t)(row * PADH) * 2u + cc * 16,
                  gsrc[matq] + (size_t)row * Ktot + k0 + cc * 8);
        }
        cpa_commit();
    };

    load_chunk(0);
    if (nch > 1) load_chunk(1);
    for (int ch = 0; ch < nch; ch++) {
        // wait until chunk ch has landed
        if (ch + 1 < nch) asm volatile("cp.async.wait_group 1;");
        else              asm volatile("cp.async.wait_group 0;");
        __syncthreads();   // chunk ch visible; all reads of stage (ch-1)%3 done
        if (ch + 2 < nch) load_chunk(ch + 2);

        uint32_t sbase = smb + (uint32_t)(ch % NSTAGE) * STAGEB;
        #pragma unroll
        for (int ks = 0; ks < 2; ks++) {
            uint32_t kb = sbase + (ks << 5);
            uint32_t Afh[2][4], Afl[2][4], Bfh[8][2], Bfl[8][2];
            #pragma unroll
            for (int mi = 0; mi < 2; mi++) {
                ldsm4(Afh[mi][0], Afh[mi][1], Afh[mi][2], Afh[mi][3], kb + aoff[mi]);
                ldsm4(Afl[mi][0], Afl[mi][1], Afl[mi][2], Afl[mi][3],
                      kb + TILEB + aoff[mi]);
            }
            #pragma unroll
            for (int njp = 0; njp < 4; njp++) {
                uint32_t r0, r1, r2, r3;
                ldsm4(r0, r1, r2, r3, kb + 2 * TILEB + boff[njp]);
                Bfh[2 * njp][0] = r0; Bfh[2 * njp][1] = r1;
                Bfh[2 * njp + 1][0] = r2; Bfh[2 * njp + 1][1] = r3;
                ldsm4(r0, r1, r2, r3, kb + 3 * TILEB + boff[njp]);
                Bfl[2 * njp][0] = r0; Bfl[2 * njp][1] = r1;
                Bfl[2 * njp + 1][0] = r2; Bfl[2 * njp + 1][1] = r3;
            }
            #pragma unroll
            for (int mi = 0; mi < 2; mi++)
                #pragma unroll
                for (int nj = 0; nj < 8; nj++) {
                    mma16816(Cf[mi][nj], Afh[mi], Bfh[nj]);
                    mma16816(Cf[mi][nj], Afh[mi], Bfl[nj]);
                    mma16816(Cf[mi][nj], Afl[mi], Bfh[nj]);
                }
        }
        __syncthreads();   // all reads of stage ch done before it is refilled
    }

    float* Cb = C_ + slice * sliceS + b * cS + (size_t)m0 * ldc + n0;
    int r0 = wm * 32 + (lane >> 2);
    int c0 = wn * 64 + ((lane & 3) << 1);
    #pragma unroll
    for (int mi = 0; mi < 2; mi++)
        #pragma unroll
        for (int nj = 0; nj < 8; nj++) {
            int r = r0 + mi * 16, c = c0 + nj * 8;
            *(float2*)&Cb[(size_t)r * ldc + c] =
                make_float2(Cf[mi][nj][0], Cf[mi][nj][1]);
            *(float2*)&Cb[(size_t)(r + 8) * ldc + c] =
                make_float2(Cf[mi][nj][2], Cf[mi][nj][3]);
        }
}

// =====================================================================
// Softmax over each S row; write P split to bf16 hi/lo.
// Row = 4096 floats = 1024 float4; 256 threads x 4 iters, stride 256.
// =====================================================================
__global__ __launch_bounds__(256) void softmax_kernel() {
    int row = blockIdx.x, b = blockIdx.y;
    size_t base = ((size_t)b * HW + row) * HW;
    const float4* src = (const float4*)(g_S + base);
    int tid = threadIdx.x;
    float4 v[4];
    float mx = -1e30f;
    #pragma unroll
    for (int i = 0; i < 4; i++) {
        v[i] = src[tid + i * 256];
        mx = fmaxf(mx, fmaxf(fmaxf(v[i].x, v[i].y), fmaxf(v[i].z, v[i].w)));
    }
    __shared__ float red[16];
    #pragma unroll
    for (int o = 16; o; o >>= 1) mx = fmaxf(mx, __shfl_xor_sync(~0u, mx, o));
    int w = tid >> 5;
    if ((tid & 31) == 0) red[w] = mx;
    __syncthreads();
    float bm = red[0];
    #pragma unroll
    for (int i = 1; i < 8; i++) bm = fmaxf(bm, red[i]);
    float sum = 0.f;
    #pragma unroll
    for (int i = 0; i < 4; i++) {
        v[i].x = __expf(v[i].x - bm); v[i].y = __expf(v[i].y - bm);
        v[i].z = __expf(v[i].z - bm); v[i].w = __expf(v[i].w - bm);
        sum += (v[i].x + v[i].y) + (v[i].z + v[i].w);
    }
    #pragma unroll
    for (int o = 16; o; o >>= 1) sum += __shfl_xor_sync(~0u, sum, o);
    if ((tid & 31) == 0) red[8 + w] = sum;
    __syncthreads();
    float bs = 0.f;
    #pragma unroll
    for (int i = 0; i < 8; i++) bs += red[8 + i];
    float rinv = 1.0f / bs;
    #pragma unroll
    for (int i = 0; i < 4; i++) {
        float p[4] = {v[i].x * rinv, v[i].y * rinv, v[i].z * rinv, v[i].w * rinv};
        bf16 h[4], l[4];
        #pragma unroll
        for (int k = 0; k < 4; k++) split_bf(p[k], h[k], l[k]);
        size_t ix = base + (size_t)(tid + i * 256) * 4;
        *(uint2*)(g_Ph + ix) = *(uint2*)h;
        *(uint2*)(g_Pl + ix) = *(uint2*)l;
    }
}

// =====================================================================
// Epilogue: sum KSPLIT partials of g_ms [sl][b][q][512] (mean|sec),
// transpose to [b][c][p]; out = std * norm(content) + mean;
// outputs concatenated (out|mean|std).
// =====================================================================
#define EPSM (2 * 256 * 33 * 4)
__global__ __launch_bounds__(256) void epilogue_kernel(
    const float* __restrict__ content, float* __restrict__ out) {
    extern __shared__ float esm[];
    float* ms = esm;              // [256][33]
    float* ss = esm + 256 * 33;
    int p0 = blockIdx.x * 32, b = blockIdx.y;
    int tid = threadIdx.x, w = tid >> 5, lane = tid & 31;
    #pragma unroll
    for (int it = 0; it < 8; it++) {
        int e = tid + (it << 8);
        int row = e >> 6;            // 0..31
        int c4 = (e & 63) << 2;      // 0..252
        float4 mv = make_float4(0.f, 0.f, 0.f, 0.f);
        float4 sv = make_float4(0.f, 0.f, 0.f, 0.f);
        #pragma unroll
        for (int sl = 0; sl < KSPLIT; sl++) {
            const float* src = g_ms +
                (((size_t)sl * NB + b) * HW + p0 + row) * 512;
            float4 t = *(const float4*)(src + c4);
            float4 u = *(const float4*)(src + 256 + c4);
            mv.x += t.x; mv.y += t.y; mv.z += t.z; mv.w += t.w;
            sv.x += u.x; sv.y += u.y; sv.z += u.z; sv.w += u.w;
        }
        ms[(c4 + 0) * 33 + row] = mv.x; ms[(c4 + 1) * 33 + row] = mv.y;
        ms[(c4 + 2) * 33 + row] = mv.z; ms[(c4 + 3) * 33 + row] = mv.w;
        ss[(c4 + 0) * 33 + row] = sv.x; ss[(c4 + 1) * 33 + row] = sv.y;
        ss[(c4 + 2) * 33 + row] = sv.z; ss[(c4 + 3) * 33 + row] = sv.w;
    }
    __syncthreads();
    const size_t TSZ = (size_t)NB * CH * HW;
    #pragma unroll 4
    for (int g = 0; g < 32; g++) {
        int c = w * 32 + g;
        float mean = ms[c * 33 + lane];
        float sec  = ss[c * 33 + lane];
        float sd   = sqrtf(fmaxf(sec - mean * mean, 0.f));
        size_t idx = ((size_t)b * CH + c) * HW + p0 + lane;
        float nc = (content[idx] - g_mean[b * CH + c]) * g_rstd[b * CH + c];
        out[idx]           = sd * nc + mean;
        out[idx + TSZ]     = mean;
        out[idx + 2 * TSZ] = sd;
    }
}

// =====================================================================
extern "C" void kernel_launch(void* const* d_in, const int* in_sizes, int n_in,
                              void* d_out, int out_size) {
    const float* content = (const float*)d_in[0];
    const float* style   = (const float*)d_in[1];
    const float* Wf = (const float*)d_in[2];
    const float* bfp = (const float*)d_in[3];
    const float* Wg = (const float*)d_in[4];
    const float* bg = (const float*)d_in[5];
    const float* Wh = (const float*)d_in[6];
    const float* bh = (const float*)d_in[7];
    float* out = (float*)d_out;

    static bool init = false;
    static bf16 *pQh, *pQl, *pKh, *pKl, *pVBh, *pVBl, *pPh, *pPl;
    static float *pS, *pMS;
    if (!init) {
        cudaGetSymbolAddress((void**)&pQh, g_Qh);
        cudaGetSymbolAddress((void**)&pQl, g_Ql);
        cudaGetSymbolAddress((void**)&pKh, g_Kh);
        cudaGetSymbolAddress((void**)&pKl, g_Kl);
        cudaGetSymbolAddress((void**)&pVBh, g_VBh);
        cudaGetSymbolAddress((void**)&pVBl, g_VBl);
        cudaGetSymbolAddress((void**)&pPh, g_Ph);
        cudaGetSymbolAddress((void**)&pPl, g_Pl);
        cudaGetSymbolAddress((void**)&pS, g_S);
        cudaGetSymbolAddress((void**)&pMS, g_ms);
        cudaFuncSetAttribute(mma_gemm,
                             cudaFuncAttributeMaxDynamicSharedMemorySize, GSMEM);
        cudaFuncSetAttribute(epilogue_kernel,
                             cudaFuncAttributeMaxDynamicSharedMemorySize, EPSM);
        init = true;
    }

    stats_kernel<<<2 * NBC, 256>>>(content, style);
    qkv_gemm<<<dim3(HW / 128, CH / 64, 3 * NB), 256>>>(content, style,
                                                       Wf, bfp, Wg, bg, Wh, bh);
    // GEMM1: S = Qn . Kn^T   (M=N=4096, K=256, no split)
    mma_gemm<<<dim3(HW / 128, HW / 128, NB), 256, GSMEM>>>(
        pQh, pQl, pKh, pKl, pS, CH, CH, HW,
        (unsigned long long)HW * CH, (unsigned long long)HW * CH,
        (unsigned long long)HW * HW, 0ull, 1);
    softmax_kernel<<<dim3(HW, NB), 256>>>();
    // GEMM2: [mean|sec] = P . [V^T ; V2^T]^T  (M=4096, N=512, K=4096, split 4)
    mma_gemm<<<dim3(512 / 128, HW / 128, NB * KSPLIT), 256, GSMEM>>>(
        pPh, pPl, pVBh, pVBl, pMS, HW / KSPLIT, HW, 512,
        (unsigned long long)HW * HW, (unsigned long long)512 * HW,
        (unsigned long long)HW * 512, (unsigned long long)NB * HW * 512, KSPLIT);
    epilogue_kernel<<<dim3(HW / 32, NB), 256, EPSM>>>(content, out);
}

// round 9
// speedup vs baseline: 2.2803x; 1.0518x over previous
#include <cuda_runtime.h>
#include <cuda_bf16.h>
#include <math.h>
#include <stdint.h>
#include <string.h>

#define HW 4096
#define CH 256
#define NB 4
#define NBC (NB*CH)
#define KSPLIT 4

typedef __nv_bfloat16 bf16;

// ---- scratch (static device globals; no allocation) ----
__device__ float g_mean[2 * NBC];
__device__ float g_rstd[2 * NBC];
__device__ bf16 g_Qh[(size_t)NB * HW * CH];
__device__ bf16 g_Ql[(size_t)NB * HW * CH];
__device__ bf16 g_Kh[(size_t)NB * HW * CH];
__device__ bf16 g_Kl[(size_t)NB * HW * CH];
// B for GEMM2: rows 0..255 = V^T [c][p], rows 256..511 = (V^2)^T
__device__ bf16 g_VBh[(size_t)NB * 512 * HW];
__device__ bf16 g_VBl[(size_t)NB * 512 * HW];
__device__ float g_S[(size_t)NB * HW * HW];
__device__ float g_rmax[(size_t)NB * HW];
__device__ float g_rinv[(size_t)NB * HW];
// split-K partials: [slice][b][q][0:256)=mean, [256:512)=sec
__device__ float g_ms[(size_t)KSPLIT * NB * HW * 512];

// ---------------- helpers ----------------
__device__ __forceinline__ uint32_t smem_u32(const void* p) {
    return (uint32_t)__cvta_generic_to_shared(p);
}
__device__ __forceinline__ void cpa16(uint32_t dst, const void* src) {
    asm volatile("cp.async.cg.shared.global [%0], [%1], 16;" :: "r"(dst), "l"(src));
}
__device__ __forceinline__ void cpa_commit() { asm volatile("cp.async.commit_group;"); }

__device__ __forceinline__ unsigned long long ffma2(unsigned long long a,
                                                    unsigned long long b,
                                                    unsigned long long c) {
    unsigned long long d;
    asm("fma.rn.f32x2 %0, %1, %2, %3;" : "=l"(d) : "l"(a), "l"(b), "l"(c));
    return d;
}
__device__ __forceinline__ unsigned long long fpack2(float x) {
    unsigned long long d;
    unsigned int xi = __float_as_uint(x);
    asm("mov.b64 %0, {%1, %1};" : "=l"(d) : "r"(xi));
    return d;
}
__device__ __forceinline__ float2 funpack(unsigned long long v) {
    unsigned int lo, hi;
    asm("mov.b64 {%0, %1}, %2;" : "=r"(lo), "=r"(hi) : "l"(v));
    float2 r; r.x = __uint_as_float(lo); r.y = __uint_as_float(hi);
    return r;
}
__device__ __forceinline__ void ldsm4(uint32_t& r0, uint32_t& r1, uint32_t& r2,
                                      uint32_t& r3, uint32_t a) {
    asm volatile("ldmatrix.sync.aligned.m8n8.x4.shared.b16 {%0,%1,%2,%3}, [%4];"
                 : "=r"(r0), "=r"(r1), "=r"(r2), "=r"(r3) : "r"(a));
}
__device__ __forceinline__ void mma16816(float* c, const uint32_t* a, const uint32_t* b) {
    asm volatile("mma.sync.aligned.m16n8k16.row.col.f32.bf16.bf16.f32 "
                 "{%0,%1,%2,%3}, {%4,%5,%6,%7}, {%8,%9}, {%0,%1,%2,%3};"
                 : "+f"(c[0]), "+f"(c[1]), "+f"(c[2]), "+f"(c[3])
                 : "r"(a[0]), "r"(a[1]), "r"(a[2]), "r"(a[3]),
                   "r"(b[0]), "r"(b[1]));
}
__device__ __forceinline__ void split_bf(float x, bf16& h, bf16& l) {
    h = __float2bfloat16_rn(x);
    l = __float2bfloat16_rn(x - __bfloat162float(h));
}
__device__ __forceinline__ uint32_t pack_bf(bf16 a, bf16 b) {
    __nv_bfloat162 t; t.x = a; t.y = b;
    uint32_t u; memcpy(&u, &t, 4); return u;
}

// =====================================================================
// Stage 1: per-(b,c) mean / rstd (ddof=1, +1e-5)
// =====================================================================
__global__ void stats_kernel(const float* __restrict__ content,
                             const float* __restrict__ style) {
    int id = blockIdx.x;
    const float* base = (id < NBC ? content : style) + (size_t)(id & (NBC - 1)) * HW;
    float s = 0.f, s2 = 0.f;
    const float4* b4 = (const float4*)base;
    for (int i = threadIdx.x; i < HW / 4; i += 256) {
        float4 v = b4[i];
        s  += v.x + v.y + v.z + v.w;
        s2 += v.x * v.x + v.y * v.y + v.z * v.z + v.w * v.w;
    }
    #pragma unroll
    for (int o = 16; o; o >>= 1) {
        s  += __shfl_xor_sync(~0u, s, o);
        s2 += __shfl_xor_sync(~0u, s2, o);
    }
    __shared__ float sh[8][2];
    int w = threadIdx.x >> 5, l = threadIdx.x & 31;
    if (l == 0) { sh[w][0] = s; sh[w][1] = s2; }
    __syncthreads();
    if (threadIdx.x == 0) {
        s = 0.f; s2 = 0.f;
        #pragma unroll
        for (int i = 0; i < 8; i++) { s += sh[i][0]; s2 += sh[i][1]; }
        float m   = s / (float)HW;
        float var = (s2 - (float)HW * m * m) / (float)(HW - 1);
        g_mean[id] = m;
        g_rstd[id] = rsqrtf(var + 1e-5f);
    }
}

// =====================================================================
// Stage 2: Q/K/V 1x1 convs (f32x2 inner loop); split-bf16 outputs.
// =====================================================================
__global__ __launch_bounds__(256) void qkv_gemm(
    const float* __restrict__ content, const float* __restrict__ style,
    const float* __restrict__ Wf, const float* __restrict__ bfb,
    const float* __restrict__ Wg, const float* __restrict__ bg,
    const float* __restrict__ Wh, const float* __restrict__ bh)
{
    int z = blockIdx.z;
    int mat = z % 3, b = z / 3;
    const float *X, *W, *bias;
    int soff;
    if (mat == 0)      { X = content; W = Wf; bias = bfb; soff = 0;   }
    else if (mat == 1) { X = style;   W = Wg; bias = bg;  soff = NBC; }
    else               { X = style;   W = Wh; bias = bh;  soff = -1;  }
    X += (size_t)b * CH * HW;
    int p0 = blockIdx.x * 128, o0 = blockIdx.y * 64;

    __shared__ float Xs[32][132];
    __shared__ float Ws[64][36];

    int tid = threadIdx.x;
    int tx  = tid & 15, ty = tid >> 4;
    unsigned long long acc2[4][4];
    #pragma unroll
    for (int u = 0; u < 4; u++)
        #pragma unroll
        for (int v = 0; v < 4; v++) acc2[u][v] = 0ull;

    for (int c0 = 0; c0 < CH; c0 += 32) {
        __syncthreads();
        #pragma unroll
        for (int r = 0; r < 4; r++) {
            int e = tid + 256 * r;
            int row = e >> 5, c4 = e & 31;
            float4 v = *(const float4*)(X + (size_t)(c0 + row) * HW + p0 + c4 * 4);
            if (soff >= 0) {
                float m  = g_mean[soff + b * CH + c0 + row];
                float rs = g_rstd[soff + b * CH + c0 + row];
                v.x = (v.x - m) * rs; v.y = (v.y - m) * rs;
                v.z = (v.z - m) * rs; v.w = (v.w - m) * rs;
            }
            *(float4*)&Xs[row][c4 * 4] = v;
        }
        #pragma unroll
        for (int r = 0; r < 2; r++) {
            int e = tid + 256 * r;
            int row = e >> 3, c4 = e & 7;
            *(float4*)&Ws[row][c4 * 4] =
                *(const float4*)(W + (size_t)(o0 + row) * CH + c0 + c4 * 4);
        }
        __syncthreads();
        #pragma unroll
        for (int cc = 0; cc < 32; cc++) {
            ulonglong2 x01 = *(ulonglong2*)&Xs[cc][tx * 8];
            ulonglong2 x23 = *(ulonglong2*)&Xs[cc][tx * 8 + 4];
            unsigned long long xv2[4] = {x01.x, x01.y, x23.x, x23.y};
            unsigned long long wp0 = fpack2(Ws[ty * 4 + 0][cc]);
            unsigned long long wp1 = fpack2(Ws[ty * 4 + 1][cc]);
            unsigned long long wp2 = fpack2(Ws[ty * 4 + 2][cc]);
            unsigned long long wp3 = fpack2(Ws[ty * 4 + 3][cc]);
            #pragma unroll
            for (int u = 0; u < 4; u++) {
                acc2[u][0] = ffma2(xv2[u], wp0, acc2[u][0]);
                acc2[u][1] = ffma2(xv2[u], wp1, acc2[u][1]);
                acc2[u][2] = ffma2(xv2[u], wp2, acc2[u][2]);
                acc2[u][3] = ffma2(xv2[u], wp3, acc2[u][3]);
            }
        }
    }
    float bv[4] = {bias[o0 + ty * 4 + 0], bias[o0 + ty * 4 + 1],
                   bias[o0 + ty * 4 + 2], bias[o0 + ty * 4 + 3]};
    float accv[8][4];
    #pragma unroll
    for (int u = 0; u < 4; u++)
        #pragma unroll
        for (int v = 0; v < 4; v++) {
            float2 t = funpack(acc2[u][v]);
            accv[2 * u][v] = t.x + bv[v];
            accv[2 * u + 1][v] = t.y + bv[v];
        }

    if (mat < 2) {
        bf16* oh = (mat ? g_Kh : g_Qh) + (size_t)b * HW * CH;
        bf16* ol = (mat ? g_Kl : g_Ql) + (size_t)b * HW * CH;
        #pragma unroll
        for (int u = 0; u < 8; u++) {
            size_t ix = (size_t)(p0 + tx * 8 + u) * CH + o0 + ty * 4;
            bf16 h[4], l[4];
            #pragma unroll
            for (int v = 0; v < 4; v++) split_bf(accv[u][v], h[v], l[v]);
            *(uint2*)(oh + ix) = *(uint2*)h;
            *(uint2*)(ol + ix) = *(uint2*)l;
        }
    } else {
        size_t vb = (size_t)b * 512 * HW;
        #pragma unroll
        for (int v = 0; v < 4; v++) {
            int c = o0 + ty * 4 + v;
            size_t ix  = vb + (size_t)c * HW + p0 + tx * 8;
            size_t ix2 = vb + (size_t)(c + 256) * HW + p0 + tx * 8;
            bf16 hv[8], lv[8], h2[8], l2[8];
            #pragma unroll
            for (int u = 0; u < 8; u++) {
                float x = accv[u][v];
                split_bf(x, hv[u], lv[u]);
                split_bf(x * x, h2[u], l2[u]);
            }
            *(uint4*)(g_VBh + ix)  = *(uint4*)hv;
            *(uint4*)(g_VBl + ix)  = *(uint4*)lv;
            *(uint4*)(g_VBh + ix2) = *(uint4*)h2;
            *(uint4*)(g_VBl + ix2) = *(uint4*)l2;
        }
    }
}

// =====================================================================
// GEMM1: S = (Qh+Ql).(Kh+Kl)^T, 128x128 block, 2-stage, 2 CTAs/SM.
// =====================================================================
#define PADH  40                    // halves per smem row (32 data + 8 pad)
#define TILEB (128 * PADH * 2)      // 10240 B per matrix tile
#define STAGEB (4 * TILEB)          // 40960 B
#define GSMEM (2 * STAGEB)          // 81920 B

__global__ __launch_bounds__(256, 2) void mma_gemm(
    const bf16* __restrict__ Ah_, const bf16* __restrict__ Al_,
    const bf16* __restrict__ Bh_, const bf16* __restrict__ Bl_,
    float* __restrict__ C_)
{
    extern __shared__ char gsm[];
    uint32_t smb = smem_u32(gsm);
    const int K = CH;
    int b = blockIdx.z, m0 = blockIdx.y * 128, n0 = blockIdx.x * 128;
    int tid = threadIdx.x, lane = tid & 31, wid = tid >> 5;
    int wm = wid & 3, wn = wid >> 2;

    const bf16* gsrc[4];
    gsrc[0] = Ah_ + (size_t)b * HW * CH + (size_t)m0 * K;
    gsrc[1] = Al_ + (size_t)b * HW * CH + (size_t)m0 * K;
    gsrc[2] = Bh_ + (size_t)b * HW * CH + (size_t)n0 * K;
    gsrc[3] = Bl_ + (size_t)b * HW * CH + (size_t)n0 * K;

    float Cf[2][8][4];
    #pragma unroll
    for (int mi = 0; mi < 2; mi++)
        #pragma unroll
        for (int nj = 0; nj < 8; nj++)
            #pragma unroll
            for (int q = 0; q < 4; q++) Cf[mi][nj][q] = 0.f;

    uint32_t aoff[2], boff[4];
    #pragma unroll
    for (int mi = 0; mi < 2; mi++)
        aoff[mi] = ((uint32_t)(wm * 32 + mi * 16 + (lane & 15)) * PADH +
                    ((lane >> 4) << 3)) * 2u;
    #pragma unroll
    for (int njp = 0; njp < 4; njp++)
        boff[njp] = ((uint32_t)(wn * 64 + njp * 16 + (lane & 7) + ((lane >> 4) << 3)) * PADH +
                     (((lane >> 3) & 1) << 3)) * 2u;

    const int nch = K >> 5;   // 8

    auto load_chunk = [&](int ch) {
        int k0 = ch << 5;
        uint32_t dbase = smb + (uint32_t)(ch & 1) * STAGEB;
        #pragma unroll
        for (int t = 0; t < 8; t++) {
            int e = tid + (t << 8);
            int matq = e >> 9, rem = e & 511;
            int row = rem >> 2, cc = rem & 3;
            cpa16(dbase + (uint32_t)matq * TILEB + (uint32_t)(row * PADH) * 2u + cc * 16,
                  gsrc[matq] + (size_t)row * K + k0 + cc * 8);
        }
        cpa_commit();
    };

    load_chunk(0);
    load_chunk(1);
    for (int ch = 0; ch < nch; ch++) {
        if (ch + 1 < nch) asm volatile("cp.async.wait_group 1;");
        else              asm volatile("cp.async.wait_group 0;");
        __syncthreads();

        uint32_t sbase = smb + (uint32_t)(ch & 1) * STAGEB;
        #pragma unroll
        for (int ks = 0; ks < 2; ks++) {
            uint32_t kb = sbase + (ks << 5);
            uint32_t Afh[2][4], Afl[2][4], Bfh[8][2], Bfl[8][2];
            #pragma unroll
            for (int mi = 0; mi < 2; mi++) {
                ldsm4(Afh[mi][0], Afh[mi][1], Afh[mi][2], Afh[mi][3], kb + aoff[mi]);
                ldsm4(Afl[mi][0], Afl[mi][1], Afl[mi][2], Afl[mi][3],
                      kb + TILEB + aoff[mi]);
            }
            #pragma unroll
            for (int njp = 0; njp < 4; njp++) {
                uint32_t r0, r1, r2, r3;
                ldsm4(r0, r1, r2, r3, kb + 2 * TILEB + boff[njp]);
                Bfh[2 * njp][0] = r0; Bfh[2 * njp][1] = r1;
                Bfh[2 * njp + 1][0] = r2; Bfh[2 * njp + 1][1] = r3;
                ldsm4(r0, r1, r2, r3, kb + 3 * TILEB + boff[njp]);
                Bfl[2 * njp][0] = r0; Bfl[2 * njp][1] = r1;
                Bfl[2 * njp + 1][0] = r2; Bfl[2 * njp + 1][1] = r3;
            }
            #pragma unroll
            for (int mi = 0; mi < 2; mi++)
                #pragma unroll
                for (int nj = 0; nj < 8; nj++) {
                    mma16816(Cf[mi][nj], Afh[mi], Bfh[nj]);
                    mma16816(Cf[mi][nj], Afh[mi], Bfl[nj]);
                    mma16816(Cf[mi][nj], Afl[mi], Bfh[nj]);
                }
        }
        __syncthreads();
        if (ch + 2 < nch) load_chunk(ch + 2);
    }

    float* Cb = C_ + (size_t)b * HW * HW + (size_t)m0 * HW + n0;
    int r0 = wm * 32 + (lane >> 2);
    int c0 = wn * 64 + ((lane & 3) << 1);
    #pragma unroll
    for (int mi = 0; mi < 2; mi++)
        #pragma unroll
        for (int nj = 0; nj < 8; nj++) {
            int r = r0 + mi * 16, c = c0 + nj * 8;
            *(float2*)&Cb[(size_t)r * HW + c] =
                make_float2(Cf[mi][nj][0], Cf[mi][nj][1]);
            *(float2*)&Cb[(size_t)(r + 8) * HW + c] =
                make_float2(Cf[mi][nj][2], Cf[mi][nj][3]);
        }
}

// =====================================================================
// Row stats: per S row, rowmax and 1/sum(exp(s-max)).
// =====================================================================
__global__ __launch_bounds__(256) void rowstat_kernel() {
    int row = blockIdx.x, b = blockIdx.y;
    size_t base = ((size_t)b * HW + row) * HW;
    const float4* src = (const float4*)(g_S + base);
    int tid = threadIdx.x;
    float4 v[4];
    float mx = -1e30f;
    #pragma unroll
    for (int i = 0; i < 4; i++) {
        v[i] = src[tid + i * 256];
        mx = fmaxf(mx, fmaxf(fmaxf(v[i].x, v[i].y), fmaxf(v[i].z, v[i].w)));
    }
    __shared__ float red[16];
    #pragma unroll
    for (int o = 16; o; o >>= 1) mx = fmaxf(mx, __shfl_xor_sync(~0u, mx, o));
    int w = tid >> 5;
    if ((tid & 31) == 0) red[w] = mx;
    __syncthreads();
    float bm = red[0];
    #pragma unroll
    for (int i = 1; i < 8; i++) bm = fmaxf(bm, red[i]);
    float sum = 0.f;
    #pragma unroll
    for (int i = 0; i < 4; i++) {
        sum += __expf(v[i].x - bm) + __expf(v[i].y - bm)
             + __expf(v[i].z - bm) + __expf(v[i].w - bm);
    }
    #pragma unroll
    for (int o = 16; o; o >>= 1) sum += __shfl_xor_sync(~0u, sum, o);
    if ((tid & 31) == 0) red[8 + w] = sum;
    __syncthreads();
    if (tid == 0) {
        float bs = 0.f;
        #pragma unroll
        for (int i = 0; i < 8; i++) bs += red[8 + i];
        g_rmax[(size_t)b * HW + row] = bm;
        g_rinv[(size_t)b * HW + row] = 1.0f / bs;
    }
}

// =====================================================================
// GEMM2 with fused softmax A-path:
//   [mean|sec](q, n) = sum_k exp(S[q][k]-rmax[q])*rinv[q] * VB[n][k]
// A: S fp32 via LDG reg-prefetch -> exp -> split bf16 -> smem.
// B: g_VBh/l via cp.async, 2-stage. Block 128x128, split-K by KSPLIT.
// =====================================================================
#define KLEN (HW / KSPLIT)          // 1024
#define GSMEM2 (2 * STAGEB)

__global__ __launch_bounds__(256, 1) void gemm2_mma() {
    extern __shared__ char gsm[];
    uint32_t smb = smem_u32(gsm);
    int b = blockIdx.z / KSPLIT, slice = blockIdx.z % KSPLIT;
    int koff = slice * KLEN;
    int m0 = blockIdx.y * 128, n0 = blockIdx.x * 128;
    int tid = threadIdx.x, lane = tid & 31, wid = tid >> 5;
    int wm = wid & 3, wn = wid >> 2;

    // A (S) per-thread: row r, 16-col group cg
    int r = tid >> 1, cg = (tid & 1) * 16;
    const float* Arow = g_S + ((size_t)(b * HW + m0 + r)) * HW + koff + cg;
    float rmax = g_rmax[(size_t)b * HW + m0 + r];
    float rinv = g_rinv[(size_t)b * HW + m0 + r];
    uint32_t ah_dst = smb + (uint32_t)(r * PADH + cg) * 2u;

    const bf16* Bh = g_VBh + (size_t)b * 512 * HW + (size_t)n0 * HW + koff;
    const bf16* Bl = g_VBl + (size_t)b * 512 * HW + (size_t)n0 * HW + koff;

    float Cf[2][8][4];
    #pragma unroll
    for (int mi = 0; mi < 2; mi++)
        #pragma unroll
        for (int nj = 0; nj < 8; nj++)
            #pragma unroll
            for (int q = 0; q < 4; q++) Cf[mi][nj][q] = 0.f;

    uint32_t aoff[2], boff[4];
    #pragma unroll
    for (int mi = 0; mi < 2; mi++)
        aoff[mi] = ((uint32_t)(wm * 32 + mi * 16 + (lane & 15)) * PADH +
                    ((lane >> 4) << 3)) * 2u;
    #pragma unroll
    for (int njp = 0; njp < 4; njp++)
        boff[njp] = ((uint32_t)(wn * 64 + njp * 16 + (lane & 7) + ((lane >> 4) << 3)) * PADH +
                     (((lane >> 3) & 1) << 3)) * 2u;

    const int nch = KLEN >> 5;   // 32

    auto loadB = [&](int ch) {
        int k0 = ch << 5;
        uint32_t dbase = smb + (uint32_t)(ch & 1) * STAGEB;
        #pragma unroll
        for (int t = 0; t < 4; t++) {
            int e = tid + (t << 8);
            int matq = e >> 9, rem = e & 511;
            int row = rem >> 2, cc = rem & 3;
            cpa16(dbase + (uint32_t)(2 + matq) * TILEB +
                      (uint32_t)(row * PADH) * 2u + cc * 16,
                  (matq ? Bl : Bh) + (size_t)row * HW + k0 + cc * 8);
        }
        cpa_commit();
    };

    float4 pf[4];
    auto loadS = [&](int ch) {
        #pragma unroll
        for (int j = 0; j < 4; j++)
            pf[j] = *(const float4*)(Arow + (ch << 5) + j * 4);
    };
    auto storeA = [&](int st) {
        uint32_t h8[8], l8[8];
        #pragma unroll
        for (int j = 0; j < 4; j++) {
            float4 v = pf[j];
            float p0v = __expf(v.x - rmax) * rinv;
            float p1v = __expf(v.y - rmax) * rinv;
            float p2v = __expf(v.z - rmax) * rinv;
            float p3v = __expf(v.w - rmax) * rinv;
            bf16 h0, l0, h1, l1, h2, l2, h3, l3;
            split_bf(p0v, h0, l0); split_bf(p1v, h1, l1);
            split_bf(p2v, h2, l2); split_bf(p3v, h3, l3);
            h8[2 * j]     = pack_bf(h0, h1);
            h8[2 * j + 1] = pack_bf(h2, h3);
            l8[2 * j]     = pack_bf(l0, l1);
            l8[2 * j + 1] = pack_bf(l2, l3);
        }
        uint32_t dst = ah_dst + (uint32_t)st * STAGEB;
        asm volatile("st.shared.v4.b32 [%0], {%1,%2,%3,%4};"
                     :: "r"(dst), "r"(h8[0]), "r"(h8[1]), "r"(h8[2]), "r"(h8[3]));
        asm volatile("st.shared.v4.b32 [%0], {%1,%2,%3,%4};"
                     :: "r"(dst + 16), "r"(h8[4]), "r"(h8[5]), "r"(h8[6]), "r"(h8[7]));
        asm volatile("st.shared.v4.b32 [%0], {%1,%2,%3,%4};"
                     :: "r"(dst + TILEB), "r"(l8[0]), "r"(l8[1]), "r"(l8[2]), "r"(l8[3]));
        asm volatile("st.shared.v4.b32 [%0], {%1,%2,%3,%4};"
                     :: "r"(dst + TILEB + 16), "r"(l8[4]), "r"(l8[5]), "r"(l8[6]), "r"(l8[7]));
    };

    loadS(0);
    loadB(0);
    for (int ch = 0; ch < nch; ch++) {
        if (ch + 1 < nch) loadB(ch + 1);
        storeA(ch & 1);
        if (ch + 1 < nch) loadS(ch + 1);
        if (ch + 1 < nch) asm volatile("cp.async.wait_group 1;");
        else              asm volatile("cp.async.wait_group 0;");
        __syncthreads();

        uint32_t sbase = smb + (uint32_t)(ch & 1) * STAGEB;
        #pragma unroll
        for (int ks = 0; ks < 2; ks++) {
            uint32_t kb = sbase + (ks << 5);
            uint32_t Afh[2][4], Afl[2][4], Bfh[8][2], Bfl[8][2];
            #pragma unroll
            for (int mi = 0; mi < 2; mi++) {
                ldsm4(Afh[mi][0], Afh[mi][1], Afh[mi][2], Afh[mi][3], kb + aoff[mi]);
                ldsm4(Afl[mi][0], Afl[mi][1], Afl[mi][2], Afl[mi][3],
                      kb + TILEB + aoff[mi]);
            }
            #pragma unroll
            for (int njp = 0; njp < 4; njp++) {
                uint32_t q0, q1, q2, q3;
                ldsm4(q0, q1, q2, q3, kb + 2 * TILEB + boff[njp]);
                Bfh[2 * njp][0] = q0; Bfh[2 * njp][1] = q1;
                Bfh[2 * njp + 1][0] = q2; Bfh[2 * njp + 1][1] = q3;
                ldsm4(q0, q1, q2, q3, kb + 3 * TILEB + boff[njp]);
                Bfl[2 * njp][0] = q0; Bfl[2 * njp][1] = q1;
                Bfl[2 * njp + 1][0] = q2; Bfl[2 * njp + 1][1] = q3;
            }
            #pragma unroll
            for (int mi = 0; mi < 2; mi++)
                #pragma unroll
                for (int nj = 0; nj < 8; nj++) {
                    mma16816(Cf[mi][nj], Afh[mi], Bfh[nj]);
                    mma16816(Cf[mi][nj], Afh[mi], Bfl[nj]);
                    mma16816(Cf[mi][nj], Afl[mi], Bfh[nj]);
                }
        }
        __syncthreads();
    }

    float* Cb = g_ms + ((size_t)slice * NB + b) * HW * 512 +
                (size_t)m0 * 512 + n0;
    int r0 = wm * 32 + (lane >> 2);
    int c0 = wn * 64 + ((lane & 3) << 1);
    #pragma unroll
    for (int mi = 0; mi < 2; mi++)
        #pragma unroll
        for (int nj = 0; nj < 8; nj++) {
            int rr = r0 + mi * 16, c = c0 + nj * 8;
            *(float2*)&Cb[(size_t)rr * 512 + c] =
                make_float2(Cf[mi][nj][0], Cf[mi][nj][1]);
            *(float2*)&Cb[(size_t)(rr + 8) * 512 + c] =
                make_float2(Cf[mi][nj][2], Cf[mi][nj][3]);
        }
}

// =====================================================================
// Epilogue: sum KSPLIT partials of g_ms, transpose, final outputs.
// =====================================================================
#define EPSM (2 * 256 * 33 * 4)
__global__ __launch_bounds__(256) void epilogue_kernel(
    const float* __restrict__ content, float* __restrict__ out) {
    extern __shared__ float esm[];
    float* ms = esm;              // [256][33]
    float* ss = esm + 256 * 33;
    int p0 = blockIdx.x * 32, b = blockIdx.y;
    int tid = threadIdx.x, w = tid >> 5, lane = tid & 31;
    #pragma unroll
    for (int it = 0; it < 8; it++) {
        int e = tid + (it << 8);
        int row = e >> 6;            // 0..31
        int c4 = (e & 63) << 2;      // 0..252
        float4 mv = make_float4(0.f, 0.f, 0.f, 0.f);
        float4 sv = make_float4(0.f, 0.f, 0.f, 0.f);
        #pragma unroll
        for (int sl = 0; sl < KSPLIT; sl++) {
            const float* src = g_ms +
                (((size_t)sl * NB + b) * HW + p0 + row) * 512;
            float4 t = *(const float4*)(src + c4);
            float4 u = *(const float4*)(src + 256 + c4);
            mv.x += t.x; mv.y += t.y; mv.z += t.z; mv.w += t.w;
            sv.x += u.x; sv.y += u.y; sv.z += u.z; sv.w += u.w;
        }
        ms[(c4 + 0) * 33 + row] = mv.x; ms[(c4 + 1) * 33 + row] = mv.y;
        ms[(c4 + 2) * 33 + row] = mv.z; ms[(c4 + 3) * 33 + row] = mv.w;
        ss[(c4 + 0) * 33 + row] = sv.x; ss[(c4 + 1) * 33 + row] = sv.y;
        ss[(c4 + 2) * 33 + row] = sv.z; ss[(c4 + 3) * 33 + row] = sv.w;
    }
    __syncthreads();
    const size_t TSZ = (size_t)NB * CH * HW;
    #pragma unroll 4
    for (int g = 0; g < 32; g++) {
        int c = w * 32 + g;
        float mean = ms[c * 33 + lane];
        float sec  = ss[c * 33 + lane];
        float sd   = sqrtf(fmaxf(sec - mean * mean, 0.f));
        size_t idx = ((size_t)b * CH + c) * HW + p0 + lane;
        float nc = (content[idx] - g_mean[b * CH + c]) * g_rstd[b * CH + c];
        out[idx]           = sd * nc + mean;
        out[idx + TSZ]     = mean;
        out[idx + 2 * TSZ] = sd;
    }
}

// =====================================================================
extern "C" void kernel_launch(void* const* d_in, const int* in_sizes, int n_in,
                              void* d_out, int out_size) {
    const float* content = (const float*)d_in[0];
    const float* style   = (const float*)d_in[1];
    const float* Wf = (const float*)d_in[2];
    const float* bfp = (const float*)d_in[3];
    const float* Wg = (const float*)d_in[4];
    const float* bg = (const float*)d_in[5];
    const float* Wh = (const float*)d_in[6];
    const float* bh = (const float*)d_in[7];
    float* out = (float*)d_out;

    static bool init = false;
    static bf16 *pQh, *pQl, *pKh, *pKl;
    static float *pS;
    if (!init) {
        cudaGetSymbolAddress((void**)&pQh, g_Qh);
        cudaGetSymbolAddress((void**)&pQl, g_Ql);
        cudaGetSymbolAddress((void**)&pKh, g_Kh);
        cudaGetSymbolAddress((void**)&pKl, g_Kl);
        cudaGetSymbolAddress((void**)&pS, g_S);
        cudaFuncSetAttribute(mma_gemm,
                             cudaFuncAttributeMaxDynamicSharedMemorySize, GSMEM);
        cudaFuncSetAttribute(gemm2_mma,
                             cudaFuncAttributeMaxDynamicSharedMemorySize, GSMEM2);
        cudaFuncSetAttribute(epilogue_kernel,
                             cudaFuncAttributeMaxDynamicSharedMemorySize, EPSM);
        init = true;
    }

    stats_kernel<<<2 * NBC, 256>>>(content, style);
    qkv_gemm<<<dim3(HW / 128, CH / 64, 3 * NB), 256>>>(content, style,
                                                       Wf, bfp, Wg, bg, Wh, bh);
    // GEMM1: S = Qn . Kn^T   (M=N=4096, K=256)
    mma_gemm<<<dim3(HW / 128, HW / 128, NB), 256, GSMEM>>>(
        pQh, pQl, pKh, pKl, pS);
    rowstat_kernel<<<dim3(HW, NB), 256>>>();
    // GEMM2: [mean|sec] = softmax(S) . [V^T ; V2^T]^T, fused exp A-path
    gemm2_mma<<<dim3(512 / 128, HW / 128, NB * KSPLIT), 256, GSMEM2>>>();
    epilogue_kernel<<<dim3(HW / 32, NB), 256, EPSM>>>(content, out);
}

// round 10
// speedup vs baseline: 2.4638x; 1.0805x over previous
#include <cuda_runtime.h>
#include <cuda_bf16.h>
#include <math.h>
#include <stdint.h>
#include <string.h>

#define HW 4096
#define CH 256
#define NB 4
#define NBC (NB*CH)
#define KSPLIT 4

typedef __nv_bfloat16 bf16;

// ---- scratch (static device globals; no allocation) ----
__device__ float g_mean[2 * NBC];
__device__ float g_rstd[2 * NBC];
__device__ bf16 g_Qh[(size_t)NB * HW * CH];
__device__ bf16 g_Ql[(size_t)NB * HW * CH];
__device__ bf16 g_Kh[(size_t)NB * HW * CH];
__device__ bf16 g_Kl[(size_t)NB * HW * CH];
// B for GEMM2: rows 0..255 = V^T [c][p], rows 256..511 = (V^2)^T
__device__ bf16 g_VBh[(size_t)NB * 512 * HW];
__device__ bf16 g_VBl[(size_t)NB * 512 * HW];
__device__ float g_S[(size_t)NB * HW * HW];
__device__ float g_rmax[(size_t)NB * HW];
__device__ float g_rinv[(size_t)NB * HW];
// split-K partials: [slice][b][q][0:256)=mean, [256:512)=sec
__device__ float g_ms[(size_t)KSPLIT * NB * HW * 512];

// ---------------- helpers ----------------
__device__ __forceinline__ uint32_t smem_u32(const void* p) {
    return (uint32_t)__cvta_generic_to_shared(p);
}
__device__ __forceinline__ void cpa16(uint32_t dst, const void* src) {
    asm volatile("cp.async.cg.shared.global [%0], [%1], 16;" :: "r"(dst), "l"(src));
}
__device__ __forceinline__ void cpa_commit() { asm volatile("cp.async.commit_group;"); }

__device__ __forceinline__ unsigned long long ffma2(unsigned long long a,
                                                    unsigned long long b,
                                                    unsigned long long c) {
    unsigned long long d;
    asm("fma.rn.f32x2 %0, %1, %2, %3;" : "=l"(d) : "l"(a), "l"(b), "l"(c));
    return d;
}
__device__ __forceinline__ unsigned long long fpack2(float x) {
    unsigned long long d;
    unsigned int xi = __float_as_uint(x);
    asm("mov.b64 %0, {%1, %1};" : "=l"(d) : "r"(xi));
    return d;
}
__device__ __forceinline__ float2 funpack(unsigned long long v) {
    unsigned int lo, hi;
    asm("mov.b64 {%0, %1}, %2;" : "=r"(lo), "=r"(hi) : "l"(v));
    float2 r; r.x = __uint_as_float(lo); r.y = __uint_as_float(hi);
    return r;
}
__device__ __forceinline__ void ldsm4(uint32_t& r0, uint32_t& r1, uint32_t& r2,
                                      uint32_t& r3, uint32_t a) {
    asm volatile("ldmatrix.sync.aligned.m8n8.x4.shared.b16 {%0,%1,%2,%3}, [%4];"
                 : "=r"(r0), "=r"(r1), "=r"(r2), "=r"(r3) : "r"(a));
}
__device__ __forceinline__ void mma16816(float* c, const uint32_t* a, const uint32_t* b) {
    asm volatile("mma.sync.aligned.m16n8k16.row.col.f32.bf16.bf16.f32 "
                 "{%0,%1,%2,%3}, {%4,%5,%6,%7}, {%8,%9}, {%0,%1,%2,%3};"
                 : "+f"(c[0]), "+f"(c[1]), "+f"(c[2]), "+f"(c[3])
                 : "r"(a[0]), "r"(a[1]), "r"(a[2]), "r"(a[3]),
                   "r"(b[0]), "r"(b[1]));
}
__device__ __forceinline__ void split_bf(float x, bf16& h, bf16& l) {
    h = __float2bfloat16_rn(x);
    l = __float2bfloat16_rn(x - __bfloat162float(h));
}
__device__ __forceinline__ uint32_t pack_bf(bf16 a, bf16 b) {
    __nv_bfloat162 t; t.x = a; t.y = b;
    uint32_t u; memcpy(&u, &t, 4); return u;
}

// =====================================================================
// Stage 1: per-(b,c) mean / rstd (ddof=1, +1e-5)
// =====================================================================
__global__ void stats_kernel(const float* __restrict__ content,
                             const float* __restrict__ style) {
    int id = blockIdx.x;
    const float* base = (id < NBC ? content : style) + (size_t)(id & (NBC - 1)) * HW;
    float s = 0.f, s2 = 0.f;
    const float4* b4 = (const float4*)base;
    for (int i = threadIdx.x; i < HW / 4; i += 256) {
        float4 v = b4[i];
        s  += v.x + v.y + v.z + v.w;
        s2 += v.x * v.x + v.y * v.y + v.z * v.z + v.w * v.w;
    }
    #pragma unroll
    for (int o = 16; o; o >>= 1) {
        s  += __shfl_xor_sync(~0u, s, o);
        s2 += __shfl_xor_sync(~0u, s2, o);
    }
    __shared__ float sh[8][2];
    int w = threadIdx.x >> 5, l = threadIdx.x & 31;
    if (l == 0) { sh[w][0] = s; sh[w][1] = s2; }
    __syncthreads();
    if (threadIdx.x == 0) {
        s = 0.f; s2 = 0.f;
        #pragma unroll
        for (int i = 0; i < 8; i++) { s += sh[i][0]; s2 += sh[i][1]; }
        float m   = s / (float)HW;
        float var = (s2 - (float)HW * m * m) / (float)(HW - 1);
        g_mean[id] = m;
        g_rstd[id] = rsqrtf(var + 1e-5f);
    }
}

// =====================================================================
// Stage 2: Q/K/V 1x1 convs (f32x2 inner loop); split-bf16 outputs.
// =====================================================================
__global__ __launch_bounds__(256) void qkv_gemm(
    const float* __restrict__ content, const float* __restrict__ style,
    const float* __restrict__ Wf, const float* __restrict__ bfb,
    const float* __restrict__ Wg, const float* __restrict__ bg,
    const float* __restrict__ Wh, const float* __restrict__ bh)
{
    int z = blockIdx.z;
    int mat = z % 3, b = z / 3;
    const float *X, *W, *bias;
    int soff;
    if (mat == 0)      { X = content; W = Wf; bias = bfb; soff = 0;   }
    else if (mat == 1) { X = style;   W = Wg; bias = bg;  soff = NBC; }
    else               { X = style;   W = Wh; bias = bh;  soff = -1;  }
    X += (size_t)b * CH * HW;
    int p0 = blockIdx.x * 128, o0 = blockIdx.y * 64;

    __shared__ float Xs[32][132];
    __shared__ float Ws[64][36];

    int tid = threadIdx.x;
    int tx  = tid & 15, ty = tid >> 4;
    unsigned long long acc2[4][4];
    #pragma unroll
    for (int u = 0; u < 4; u++)
        #pragma unroll
        for (int v = 0; v < 4; v++) acc2[u][v] = 0ull;

    for (int c0 = 0; c0 < CH; c0 += 32) {
        __syncthreads();
        #pragma unroll
        for (int r = 0; r < 4; r++) {
            int e = tid + 256 * r;
            int row = e >> 5, c4 = e & 31;
            float4 v = *(const float4*)(X + (size_t)(c0 + row) * HW + p0 + c4 * 4);
            if (soff >= 0) {
                float m  = g_mean[soff + b * CH + c0 + row];
                float rs = g_rstd[soff + b * CH + c0 + row];
                v.x = (v.x - m) * rs; v.y = (v.y - m) * rs;
                v.z = (v.z - m) * rs; v.w = (v.w - m) * rs;
            }
            *(float4*)&Xs[row][c4 * 4] = v;
        }
        #pragma unroll
        for (int r = 0; r < 2; r++) {
            int e = tid + 256 * r;
            int row = e >> 3, c4 = e & 7;
            *(float4*)&Ws[row][c4 * 4] =
                *(const float4*)(W + (size_t)(o0 + row) * CH + c0 + c4 * 4);
        }
        __syncthreads();
        #pragma unroll
        for (int cc = 0; cc < 32; cc++) {
            ulonglong2 x01 = *(ulonglong2*)&Xs[cc][tx * 8];
            ulonglong2 x23 = *(ulonglong2*)&Xs[cc][tx * 8 + 4];
            unsigned long long xv2[4] = {x01.x, x01.y, x23.x, x23.y};
            unsigned long long wp0 = fpack2(Ws[ty * 4 + 0][cc]);
            unsigned long long wp1 = fpack2(Ws[ty * 4 + 1][cc]);
            unsigned long long wp2 = fpack2(Ws[ty * 4 + 2][cc]);
            unsigned long long wp3 = fpack2(Ws[ty * 4 + 3][cc]);
            #pragma unroll
            for (int u = 0; u < 4; u++) {
                acc2[u][0] = ffma2(xv2[u], wp0, acc2[u][0]);
                acc2[u][1] = ffma2(xv2[u], wp1, acc2[u][1]);
                acc2[u][2] = ffma2(xv2[u], wp2, acc2[u][2]);
                acc2[u][3] = ffma2(xv2[u], wp3, acc2[u][3]);
            }
        }
    }
    float bv[4] = {bias[o0 + ty * 4 + 0], bias[o0 + ty * 4 + 1],
                   bias[o0 + ty * 4 + 2], bias[o0 + ty * 4 + 3]};
    float accv[8][4];
    #pragma unroll
    for (int u = 0; u < 4; u++)
        #pragma unroll
        for (int v = 0; v < 4; v++) {
            float2 t = funpack(acc2[u][v]);
            accv[2 * u][v] = t.x + bv[v];
            accv[2 * u + 1][v] = t.y + bv[v];
        }

    if (mat < 2) {
        bf16* oh = (mat ? g_Kh : g_Qh) + (size_t)b * HW * CH;
        bf16* ol = (mat ? g_Kl : g_Ql) + (size_t)b * HW * CH;
        #pragma unroll
        for (int u = 0; u < 8; u++) {
            size_t ix = (size_t)(p0 + tx * 8 + u) * CH + o0 + ty * 4;
            bf16 h[4], l[4];
            #pragma unroll
            for (int v = 0; v < 4; v++) split_bf(accv[u][v], h[v], l[v]);
            *(uint2*)(oh + ix) = *(uint2*)h;
            *(uint2*)(ol + ix) = *(uint2*)l;
        }
    } else {
        size_t vb = (size_t)b * 512 * HW;
        #pragma unroll
        for (int v = 0; v < 4; v++) {
            int c = o0 + ty * 4 + v;
            size_t ix  = vb + (size_t)c * HW + p0 + tx * 8;
            size_t ix2 = vb + (size_t)(c + 256) * HW + p0 + tx * 8;
            bf16 hv[8], lv[8], h2[8], l2[8];
            #pragma unroll
            for (int u = 0; u < 8; u++) {
                float x = accv[u][v];
                split_bf(x, hv[u], lv[u]);
                split_bf(x * x, h2[u], l2[u]);
            }
            *(uint4*)(g_VBh + ix)  = *(uint4*)hv;
            *(uint4*)(g_VBl + ix)  = *(uint4*)lv;
            *(uint4*)(g_VBh + ix2) = *(uint4*)h2;
            *(uint4*)(g_VBl + ix2) = *(uint4*)l2;
        }
    }
}

// =====================================================================
// GEMM1: S = (Qh+Ql).(Kh+Kl)^T, 128x128 block, 2-stage, 2 CTAs/SM.
// =====================================================================
#define PADH  40                    // halves per smem row (32 data + 8 pad)
#define TILEB (128 * PADH * 2)      // 10240 B per matrix tile
#define STAGEB (4 * TILEB)          // 40960 B
#define GSMEM (2 * STAGEB)          // 81920 B

__global__ __launch_bounds__(256, 2) void mma_gemm(
    const bf16* __restrict__ Ah_, const bf16* __restrict__ Al_,
    const bf16* __restrict__ Bh_, const bf16* __restrict__ Bl_,
    float* __restrict__ C_)
{
    extern __shared__ char gsm[];
    uint32_t smb = smem_u32(gsm);
    const int K = CH;
    int b = blockIdx.z, m0 = blockIdx.y * 128, n0 = blockIdx.x * 128;
    int tid = threadIdx.x, lane = tid & 31, wid = tid >> 5;
    int wm = wid & 3, wn = wid >> 2;

    const bf16* gsrc[4];
    gsrc[0] = Ah_ + (size_t)b * HW * CH + (size_t)m0 * K;
    gsrc[1] = Al_ + (size_t)b * HW * CH + (size_t)m0 * K;
    gsrc[2] = Bh_ + (size_t)b * HW * CH + (size_t)n0 * K;
    gsrc[3] = Bl_ + (size_t)b * HW * CH + (size_t)n0 * K;

    float Cf[2][8][4];
    #pragma unroll
    for (int mi = 0; mi < 2; mi++)
        #pragma unroll
        for (int nj = 0; nj < 8; nj++)
            #pragma unroll
            for (int q = 0; q < 4; q++) Cf[mi][nj][q] = 0.f;

    uint32_t aoff[2], boff[4];
    #pragma unroll
    for (int mi = 0; mi < 2; mi++)
        aoff[mi] = ((uint32_t)(wm * 32 + mi * 16 + (lane & 15)) * PADH +
                    ((lane >> 4) << 3)) * 2u;
    #pragma unroll
    for (int njp = 0; njp < 4; njp++)
        boff[njp] = ((uint32_t)(wn * 64 + njp * 16 + (lane & 7) + ((lane >> 4) << 3)) * PADH +
                     (((lane >> 3) & 1) << 3)) * 2u;

    const int nch = K >> 5;   // 8

    auto load_chunk = [&](int ch) {
        int k0 = ch << 5;
        uint32_t dbase = smb + (uint32_t)(ch & 1) * STAGEB;
        #pragma unroll
        for (int t = 0; t < 8; t++) {
            int e = tid + (t << 8);
            int matq = e >> 9, rem = e & 511;
            int row = rem >> 2, cc = rem & 3;
            cpa16(dbase + (uint32_t)matq * TILEB + (uint32_t)(row * PADH) * 2u + cc * 16,
                  gsrc[matq] + (size_t)row * K + k0 + cc * 8);
        }
        cpa_commit();
    };

    load_chunk(0);
    load_chunk(1);
    for (int ch = 0; ch < nch; ch++) {
        if (ch + 1 < nch) asm volatile("cp.async.wait_group 1;");
        else              asm volatile("cp.async.wait_group 0;");
        __syncthreads();

        uint32_t sbase = smb + (uint32_t)(ch & 1) * STAGEB;
        #pragma unroll
        for (int ks = 0; ks < 2; ks++) {
            uint32_t kb = sbase + (ks << 5);
            uint32_t Afh[2][4], Afl[2][4], Bfh[8][2], Bfl[8][2];
            #pragma unroll
            for (int mi = 0; mi < 2; mi++) {
                ldsm4(Afh[mi][0], Afh[mi][1], Afh[mi][2], Afh[mi][3], kb + aoff[mi]);
                ldsm4(Afl[mi][0], Afl[mi][1], Afl[mi][2], Afl[mi][3],
                      kb + TILEB + aoff[mi]);
            }
            #pragma unroll
            for (int njp = 0; njp < 4; njp++) {
                uint32_t r0, r1, r2, r3;
                ldsm4(r0, r1, r2, r3, kb + 2 * TILEB + boff[njp]);
                Bfh[2 * njp][0] = r0; Bfh[2 * njp][1] = r1;
                Bfh[2 * njp + 1][0] = r2; Bfh[2 * njp + 1][1] = r3;
                ldsm4(r0, r1, r2, r3, kb + 3 * TILEB + boff[njp]);
                Bfl[2 * njp][0] = r0; Bfl[2 * njp][1] = r1;
                Bfl[2 * njp + 1][0] = r2; Bfl[2 * njp + 1][1] = r3;
            }
            #pragma unroll
            for (int mi = 0; mi < 2; mi++)
                #pragma unroll
                for (int nj = 0; nj < 8; nj++) {
                    mma16816(Cf[mi][nj], Afh[mi], Bfh[nj]);
                    mma16816(Cf[mi][nj], Afh[mi], Bfl[nj]);
                    mma16816(Cf[mi][nj], Afl[mi], Bfh[nj]);
                }
        }
        __syncthreads();
        if (ch + 2 < nch) load_chunk(ch + 2);
    }

    float* Cb = C_ + (size_t)b * HW * HW + (size_t)m0 * HW + n0;
    int r0 = wm * 32 + (lane >> 2);
    int c0 = wn * 64 + ((lane & 3) << 1);
    #pragma unroll
    for (int mi = 0; mi < 2; mi++)
        #pragma unroll
        for (int nj = 0; nj < 8; nj++) {
            int r = r0 + mi * 16, c = c0 + nj * 8;
            *(float2*)&Cb[(size_t)r * HW + c] =
                make_float2(Cf[mi][nj][0], Cf[mi][nj][1]);
            *(float2*)&Cb[(size_t)(r + 8) * HW + c] =
                make_float2(Cf[mi][nj][2], Cf[mi][nj][3]);
        }
}

// =====================================================================
// Row stats: per S row, rowmax and 1/sum(exp(s-max)).
// =====================================================================
__global__ __launch_bounds__(256) void rowstat_kernel() {
    int row = blockIdx.x, b = blockIdx.y;
    size_t base = ((size_t)b * HW + row) * HW;
    const float4* src = (const float4*)(g_S + base);
    int tid = threadIdx.x;
    float4 v[4];
    float mx = -1e30f;
    #pragma unroll
    for (int i = 0; i < 4; i++) {
        v[i] = src[tid + i * 256];
        mx = fmaxf(mx, fmaxf(fmaxf(v[i].x, v[i].y), fmaxf(v[i].z, v[i].w)));
    }
    __shared__ float red[16];
    #pragma unroll
    for (int o = 16; o; o >>= 1) mx = fmaxf(mx, __shfl_xor_sync(~0u, mx, o));
    int w = tid >> 5;
    if ((tid & 31) == 0) red[w] = mx;
    __syncthreads();
    float bm = red[0];
    #pragma unroll
    for (int i = 1; i < 8; i++) bm = fmaxf(bm, red[i]);
    float sum = 0.f;
    #pragma unroll
    for (int i = 0; i < 4; i++) {
        sum += __expf(v[i].x - bm) + __expf(v[i].y - bm)
             + __expf(v[i].z - bm) + __expf(v[i].w - bm);
    }
    #pragma unroll
    for (int o = 16; o; o >>= 1) sum += __shfl_xor_sync(~0u, sum, o);
    if ((tid & 31) == 0) red[8 + w] = sum;
    __syncthreads();
    if (tid == 0) {
        float bs = 0.f;
        #pragma unroll
        for (int i = 0; i < 8; i++) bs += red[8 + i];
        g_rmax[(size_t)b * HW + row] = bm;
        g_rinv[(size_t)b * HW + row] = 1.0f / bs;
    }
}

// =====================================================================
// GEMM2 with fused softmax A-path, TWO n-tiles per block (128x256):
//   [mean|sec](q, n) = sum_k exp(S[q][k]-rmax[q])*rinv[q] * VB[n][k]
// A (exp'd S) converted ONCE per k-chunk and reused for both n-tiles.
// Stage: A hi/lo (2*TILEB) + 2 n-tiles B hi/lo (4*TILEB) = 6*TILEB.
// =====================================================================
#define KLEN (HW / KSPLIT)          // 1024
#define STAGE2B (6 * TILEB)         // 61440
#define GSMEM2 (2 * STAGE2B)        // 122880

__global__ __launch_bounds__(256, 1) void gemm2_mma() {
    extern __shared__ char gsm[];
    uint32_t smb = smem_u32(gsm);
    int b = blockIdx.z / KSPLIT, slice = blockIdx.z % KSPLIT;
    int koff = slice * KLEN;
    int m0 = blockIdx.y * 128, n0 = blockIdx.x * 256;
    int tid = threadIdx.x, lane = tid & 31, wid = tid >> 5;
    int wm = wid & 3, wn = wid >> 2;

    // A (S) per-thread: row r, 16-col group cg
    int r = tid >> 1, cg = (tid & 1) * 16;
    const float* Arow = g_S + ((size_t)(b * HW + m0 + r)) * HW + koff + cg;
    float rmax = g_rmax[(size_t)b * HW + m0 + r];
    float rinv = g_rinv[(size_t)b * HW + m0 + r];
    uint32_t ah_dst = smb + (uint32_t)(r * PADH + cg) * 2u;

    const bf16* Bh = g_VBh + (size_t)b * 512 * HW + (size_t)n0 * HW + koff;
    const bf16* Bl = g_VBl + (size_t)b * 512 * HW + (size_t)n0 * HW + koff;

    float Cf[2][2][8][4];   // [ntile][mi][nj][q]
    #pragma unroll
    for (int nt = 0; nt < 2; nt++)
        #pragma unroll
        for (int mi = 0; mi < 2; mi++)
            #pragma unroll
            for (int nj = 0; nj < 8; nj++)
                #pragma unroll
                for (int q = 0; q < 4; q++) Cf[nt][mi][nj][q] = 0.f;

    uint32_t aoff[2], boff[4];
    #pragma unroll
    for (int mi = 0; mi < 2; mi++)
        aoff[mi] = ((uint32_t)(wm * 32 + mi * 16 + (lane & 15)) * PADH +
                    ((lane >> 4) << 3)) * 2u;
    #pragma unroll
    for (int njp = 0; njp < 4; njp++)
        boff[njp] = ((uint32_t)(wn * 64 + njp * 16 + (lane & 7) + ((lane >> 4) << 3)) * PADH +
                     (((lane >> 3) & 1) << 3)) * 2u;

    const int nch = KLEN >> 5;   // 32

    // B loader: 4 tiles (nt0 hi, nt0 lo, nt1 hi, nt1 lo), 2048 pieces
    auto loadB = [&](int ch) {
        int k0 = ch << 5;
        uint32_t dbase = smb + (uint32_t)(ch & 1) * STAGE2B + 2 * TILEB;
        #pragma unroll
        for (int t = 0; t < 8; t++) {
            int e = tid + (t << 8);
            int matq = e >> 9, rem = e & 511;   // matq: nt*2 + hl
            int nt = matq >> 1, hl = matq & 1;
            int row = rem >> 2, cc = rem & 3;
            const bf16* src = (hl ? Bl : Bh) + (size_t)(nt * 128 + row) * HW + k0 + cc * 8;
            cpa16(dbase + (uint32_t)matq * TILEB +
                      (uint32_t)(row * PADH) * 2u + cc * 16, src);
        }
        cpa_commit();
    };

    float4 pf[4];
    auto loadS = [&](int ch) {
        #pragma unroll
        for (int j = 0; j < 4; j++)
            pf[j] = *(const float4*)(Arow + (ch << 5) + j * 4);
    };
    auto storeA = [&](int st) {
        uint32_t h8[8], l8[8];
        #pragma unroll
        for (int j = 0; j < 4; j++) {
            float4 v = pf[j];
            float p0v = __expf(v.x - rmax) * rinv;
            float p1v = __expf(v.y - rmax) * rinv;
            float p2v = __expf(v.z - rmax) * rinv;
            float p3v = __expf(v.w - rmax) * rinv;
            bf16 h0, l0, h1, l1, h2, l2, h3, l3;
            split_bf(p0v, h0, l0); split_bf(p1v, h1, l1);
            split_bf(p2v, h2, l2); split_bf(p3v, h3, l3);
            h8[2 * j]     = pack_bf(h0, h1);
            h8[2 * j + 1] = pack_bf(h2, h3);
            l8[2 * j]     = pack_bf(l0, l1);
            l8[2 * j + 1] = pack_bf(l2, l3);
        }
        uint32_t dst = ah_dst + (uint32_t)st * STAGE2B;
        asm volatile("st.shared.v4.b32 [%0], {%1,%2,%3,%4};"
                     :: "r"(dst), "r"(h8[0]), "r"(h8[1]), "r"(h8[2]), "r"(h8[3]));
        asm volatile("st.shared.v4.b32 [%0], {%1,%2,%3,%4};"
                     :: "r"(dst + 16), "r"(h8[4]), "r"(h8[5]), "r"(h8[6]), "r"(h8[7]));
        asm volatile("st.shared.v4.b32 [%0], {%1,%2,%3,%4};"
                     :: "r"(dst + TILEB), "r"(l8[0]), "r"(l8[1]), "r"(l8[2]), "r"(l8[3]));
        asm volatile("st.shared.v4.b32 [%0], {%1,%2,%3,%4};"
                     :: "r"(dst + TILEB + 16), "r"(l8[4]), "r"(l8[5]), "r"(l8[6]), "r"(l8[7]));
    };

    loadS(0);
    loadB(0);
    for (int ch = 0; ch < nch; ch++) {
        if (ch + 1 < nch) loadB(ch + 1);
        storeA(ch & 1);
        if (ch + 1 < nch) loadS(ch + 1);
        if (ch + 1 < nch) asm volatile("cp.async.wait_group 1;");
        else              asm volatile("cp.async.wait_group 0;");
        __syncthreads();

        uint32_t sbase = smb + (uint32_t)(ch & 1) * STAGE2B;
        #pragma unroll
        for (int ks = 0; ks < 2; ks++) {
            uint32_t kb = sbase + (ks << 5);
            uint32_t Afh[2][4], Afl[2][4];
            #pragma unroll
            for (int mi = 0; mi < 2; mi++) {
                ldsm4(Afh[mi][0], Afh[mi][1], Afh[mi][2], Afh[mi][3], kb + aoff[mi]);
                ldsm4(Afl[mi][0], Afl[mi][1], Afl[mi][2], Afl[mi][3],
                      kb + TILEB + aoff[mi]);
            }
            #pragma unroll
            for (int nt = 0; nt < 2; nt++) {
                uint32_t bh_base = kb + (uint32_t)(2 + 2 * nt) * TILEB;
                uint32_t Bfh[8][2], Bfl[8][2];
                #pragma unroll
                for (int njp = 0; njp < 4; njp++) {
                    uint32_t q0, q1, q2, q3;
                    ldsm4(q0, q1, q2, q3, bh_base + boff[njp]);
                    Bfh[2 * njp][0] = q0; Bfh[2 * njp][1] = q1;
                    Bfh[2 * njp + 1][0] = q2; Bfh[2 * njp + 1][1] = q3;
                    ldsm4(q0, q1, q2, q3, bh_base + TILEB + boff[njp]);
                    Bfl[2 * njp][0] = q0; Bfl[2 * njp][1] = q1;
                    Bfl[2 * njp + 1][0] = q2; Bfl[2 * njp + 1][1] = q3;
                }
                #pragma unroll
                for (int mi = 0; mi < 2; mi++)
                    #pragma unroll
                    for (int nj = 0; nj < 8; nj++) {
                        mma16816(Cf[nt][mi][nj], Afh[mi], Bfh[nj]);
                        mma16816(Cf[nt][mi][nj], Afh[mi], Bfl[nj]);
                        mma16816(Cf[nt][mi][nj], Afl[mi], Bfh[nj]);
                    }
            }
        }
        __syncthreads();
    }

    int r0 = wm * 32 + (lane >> 2);
    int c0 = wn * 64 + ((lane & 3) << 1);
    #pragma unroll
    for (int nt = 0; nt < 2; nt++) {
        float* Cb = g_ms + ((size_t)slice * NB + b) * HW * 512 +
                    (size_t)m0 * 512 + n0 + nt * 128;
        #pragma unroll
        for (int mi = 0; mi < 2; mi++)
            #pragma unroll
            for (int nj = 0; nj < 8; nj++) {
                int rr = r0 + mi * 16, c = c0 + nj * 8;
                *(float2*)&Cb[(size_t)rr * 512 + c] =
                    make_float2(Cf[nt][mi][nj][0], Cf[nt][mi][nj][1]);
                *(float2*)&Cb[(size_t)(rr + 8) * 512 + c] =
                    make_float2(Cf[nt][mi][nj][2], Cf[nt][mi][nj][3]);
            }
    }
}

// =====================================================================
// Epilogue: sum KSPLIT partials of g_ms, transpose, final outputs.
// =====================================================================
#define EPSM (2 * 256 * 33 * 4)
__global__ __launch_bounds__(256) void epilogue_kernel(
    const float* __restrict__ content, float* __restrict__ out) {
    extern __shared__ float esm[];
    float* ms = esm;              // [256][33]
    float* ss = esm + 256 * 33;
    int p0 = blockIdx.x * 32, b = blockIdx.y;
    int tid = threadIdx.x, w = tid >> 5, lane = tid & 31;
    #pragma unroll
    for (int it = 0; it < 8; it++) {
        int e = tid + (it << 8);
        int row = e >> 6;            // 0..31
        int c4 = (e & 63) << 2;      // 0..252
        float4 mv = make_float4(0.f, 0.f, 0.f, 0.f);
        float4 sv = make_float4(0.f, 0.f, 0.f, 0.f);
        #pragma unroll
        for (int sl = 0; sl < KSPLIT; sl++) {
            const float* src = g_ms +
                (((size_t)sl * NB + b) * HW + p0 + row) * 512;
            float4 t = *(const float4*)(src + c4);
            float4 u = *(const float4*)(src + 256 + c4);
            mv.x += t.x; mv.y += t.y; mv.z += t.z; mv.w += t.w;
            sv.x += u.x; sv.y += u.y; sv.z += u.z; sv.w += u.w;
        }
        ms[(c4 + 0) * 33 + row] = mv.x; ms[(c4 + 1) * 33 + row] = mv.y;
        ms[(c4 + 2) * 33 + row] = mv.z; ms[(c4 + 3) * 33 + row] = mv.w;
        ss[(c4 + 0) * 33 + row] = sv.x; ss[(c4 + 1) * 33 + row] = sv.y;
        ss[(c4 + 2) * 33 + row] = sv.z; ss[(c4 + 3) * 33 + row] = sv.w;
    }
    __syncthreads();
    const size_t TSZ = (size_t)NB * CH * HW;
    #pragma unroll 4
    for (int g = 0; g < 32; g++) {
        int c = w * 32 + g;
        float mean = ms[c * 33 + lane];
        float sec  = ss[c * 33 + lane];
        float sd   = sqrtf(fmaxf(sec - mean * mean, 0.f));
        size_t idx = ((size_t)b * CH + c) * HW + p0 + lane;
        float nc = (content[idx] - g_mean[b * CH + c]) * g_rstd[b * CH + c];
        out[idx]           = sd * nc + mean;
        out[idx + TSZ]     = mean;
        out[idx + 2 * TSZ] = sd;
    }
}

// =====================================================================
extern "C" void kernel_launch(void* const* d_in, const int* in_sizes, int n_in,
                              void* d_out, int out_size) {
    const float* content = (const float*)d_in[0];
    const float* style   = (const float*)d_in[1];
    const float* Wf = (const float*)d_in[2];
    const float* bfp = (const float*)d_in[3];
    const float* Wg = (const float*)d_in[4];
    const float* bg = (const float*)d_in[5];
    const float* Wh = (const float*)d_in[6];
    const float* bh = (const float*)d_in[7];
    float* out = (float*)d_out;

    static bool init = false;
    static bf16 *pQh, *pQl, *pKh, *pKl;
    static float *pS;
    if (!init) {
        cudaGetSymbolAddress((void**)&pQh, g_Qh);
        cudaGetSymbolAddress((void**)&pQl, g_Ql);
        cudaGetSymbolAddress((void**)&pKh, g_Kh);
        cudaGetSymbolAddress((void**)&pKl, g_Kl);
        cudaGetSymbolAddress((void**)&pS, g_S);
        cudaFuncSetAttribute(mma_gemm,
                             cudaFuncAttributeMaxDynamicSharedMemorySize, GSMEM);
        cudaFuncSetAttribute(gemm2_mma,
                             cudaFuncAttributeMaxDynamicSharedMemorySize, GSMEM2);
        cudaFuncSetAttribute(epilogue_kernel,
                             cudaFuncAttributeMaxDynamicSharedMemorySize, EPSM);
        init = true;
    }

    stats_kernel<<<2 * NBC, 256>>>(content, style);
    qkv_gemm<<<dim3(HW / 128, CH / 64, 3 * NB), 256>>>(content, style,
                                                       Wf, bfp, Wg, bg, Wh, bh);
    // GEMM1: S = Qn . Kn^T   (M=N=4096, K=256)
    mma_gemm<<<dim3(HW / 128, HW / 128, NB), 256, GSMEM>>>(
        pQh, pQl, pKh, pKl, pS);
    rowstat_kernel<<<dim3(HW, NB), 256>>>();
    // GEMM2: [mean|sec] = softmax(S) . [V^T ; V2^T]^T, fused exp A-path,
    // two n-tiles per block (A converted once, reused).
    gemm2_mma<<<dim3(512 / 256, HW / 128, NB * KSPLIT), 256, GSMEM2>>>();
    epilogue_kernel<<<dim3(HW / 32, NB), 256, EPSM>>>(content, out);
}